// round 13
// baseline (speedup 1.0000x reference)
#include <cuda_runtime.h>
#include <cuda_bf16.h>
#include <math.h>
#include <stdint.h>

#define BB 4096
#define HH 1024
#define NG 5120
#define BH (4096*1024)

// GEMM tiling: CTA 128x128, 8 warps (2x4), warp 64x32, K-step 16, 4-stage, 2 CTAs/SM
// single __syncthreads per stage (4-buffer rotation makes the WAR barrier redundant)
#define RS 24                        // padded smem row stride (bf16) = 48B
#define ARR_BYTES (128*RS*2)         // 6144 per tile array
#define STG_BYTES (4*ARR_BYTES)      // 24576 per stage (Ah,Al,Wh,Wl)
#define NSTAGE 4
#define SMEM_BYTES (NSTAGE*STG_BYTES) // 98304

// ---------------- scratch (device globals; no allocs) ----------------
__device__ __nv_bfloat16 s_x_hi[(size_t)BB*HH],  s_x_lo[(size_t)BB*HH];
__device__ __nv_bfloat16 s_h_hi[(size_t)BB*HH],  s_h_lo[(size_t)BB*HH];
__device__ __nv_bfloat16 s_sg_hi[(size_t)BB*HH], s_sg_lo[(size_t)BB*HH];
__device__ __nv_bfloat16 s_r1_hi[(size_t)BB*HH], s_r1_lo[(size_t)BB*HH];
__device__ __nv_bfloat16 s_r2_hi[(size_t)BB*HH], s_r2_lo[(size_t)BB*HH];
__device__ __nv_bfloat16 w_Wx_hi[(size_t)NG*HH], w_Wx_lo[(size_t)NG*HH];
__device__ __nv_bfloat16 w_Ux_hi[(size_t)NG*HH], w_Ux_lo[(size_t)NG*HH];
__device__ __nv_bfloat16 w_a1_hi[(size_t)HH*2048], w_a1_lo[(size_t)HH*2048];
__device__ __nv_bfloat16 w_sw_hi[(size_t)HH*HH], w_sw_lo[(size_t)HH*HH];
__device__ __nv_bfloat16 w_r1_hi[(size_t)HH*HH], w_r1_lo[(size_t)HH*HH];
__device__ __nv_bfloat16 w_r2_hi[(size_t)HH*HH], w_r2_lo[(size_t)HH*HH];
__device__ __nv_bfloat16 w_r3_hi[(size_t)HH*HH], w_r3_lo[(size_t)HH*HH];
__device__ float g_gates[(size_t)BB*NG];
__device__ float g_ah[(size_t)BB*HH];
__device__ float g_alpha[BB];
// sync counters: [0..32) gates_rb  [32..64) ah_rb  [64..96) ssg_rb
//                [96..128) r1_rb   [128..160) alpha_ch  [160..192) r2_rb
__device__ int g_cnt[256];

// ---------------- helpers ----------------
__device__ __forceinline__ uint32_t smem_u32(const void* p) {
    uint32_t a;
    asm("{ .reg .u64 t; cvta.to.shared.u64 t, %1; cvt.u32.u64 %0, t; }" : "=r"(a) : "l"(p));
    return a;
}
__device__ __forceinline__ void ldsm4(uint32_t& r0, uint32_t& r1, uint32_t& r2, uint32_t& r3, uint32_t a) {
    asm volatile("ldmatrix.sync.aligned.m8n8.x4.shared.b16 {%0,%1,%2,%3}, [%4];"
        : "=r"(r0), "=r"(r1), "=r"(r2), "=r"(r3) : "r"(a));
}
__device__ __forceinline__ void mma16816(float* c, const uint32_t* a, const uint32_t* b) {
    asm volatile("mma.sync.aligned.m16n8k16.row.col.f32.bf16.bf16.f32 "
        "{%0,%1,%2,%3}, {%4,%5,%6,%7}, {%8,%9}, {%0,%1,%2,%3};"
        : "+f"(c[0]), "+f"(c[1]), "+f"(c[2]), "+f"(c[3])
        : "r"(a[0]), "r"(a[1]), "r"(a[2]), "r"(a[3]), "r"(b[0]), "r"(b[1]));
}
#define CP_ASYNC16(dst, src) \
    asm volatile("cp.async.cg.shared.global [%0], [%1], 16;" :: "r"(dst), "l"(src))
#define CP_COMMIT()  asm volatile("cp.async.commit_group;" ::: "memory")
#define CP_WAIT(n)   asm volatile("cp.async.wait_group %0;" :: "n"(n) : "memory")

__device__ __forceinline__ int ld_acq(const int* p) {
    int v; asm volatile("ld.acquire.gpu.global.s32 %0, [%1];" : "=r"(v) : "l"(p) : "memory");
    return v;
}
__device__ __forceinline__ void spin_wait(const int* c, int target) {
    if (threadIdx.x == 0) {
        while (ld_acq(c) < target) __nanosleep(128);
    }
    __syncthreads();
}
__device__ __forceinline__ void signal_cnt(int* c) {
    __threadfence();
    __syncthreads();
    if (threadIdx.x == 0) atomicAdd(c, 1);
}

__device__ __forceinline__ float tanh_fast(float v) {
    return 2.f / (1.f + __expf(-2.f * v)) - 1.f;
}

__device__ __forceinline__ void split2(float v0, float v1, __nv_bfloat162& hi, __nv_bfloat162& lo) {
    __nv_bfloat16 h0 = __float2bfloat16_rn(v0), h1 = __float2bfloat16_rn(v1);
    __nv_bfloat16 l0 = __float2bfloat16_rn(v0 - __bfloat162float(h0));
    __nv_bfloat16 l1 = __float2bfloat16_rn(v1 - __bfloat162float(h1));
    hi = __nv_bfloat162(h0, h1); lo = __nv_bfloat162(l0, l1);
}
__device__ __forceinline__ uint32_t b2u(__nv_bfloat162 v) {
    uint32_t u; *(__nv_bfloat162*)&u = v; return u;
}
// 8 floats -> 16B hi + 16B lo, paired bf16x2 conversions
__device__ __forceinline__ void split8(float4 a, float4 b, uint4& hi, uint4& lo) {
    float2 a01 = make_float2(a.x, a.y), a23 = make_float2(a.z, a.w);
    float2 b01 = make_float2(b.x, b.y), b23 = make_float2(b.z, b.w);
    __nv_bfloat162 h0 = __float22bfloat162_rn(a01);
    __nv_bfloat162 h1 = __float22bfloat162_rn(a23);
    __nv_bfloat162 h2 = __float22bfloat162_rn(b01);
    __nv_bfloat162 h3 = __float22bfloat162_rn(b23);
    float2 f0 = __bfloat1622float2(h0), f1 = __bfloat1622float2(h1);
    float2 f2 = __bfloat1622float2(h2), f3 = __bfloat1622float2(h3);
    __nv_bfloat162 l0 = __float22bfloat162_rn(make_float2(a01.x - f0.x, a01.y - f0.y));
    __nv_bfloat162 l1 = __float22bfloat162_rn(make_float2(a23.x - f1.x, a23.y - f1.y));
    __nv_bfloat162 l2 = __float22bfloat162_rn(make_float2(b01.x - f2.x, b01.y - f2.y));
    __nv_bfloat162 l3 = __float22bfloat162_rn(make_float2(b23.x - f3.x, b23.y - f3.y));
    hi.x = b2u(h0); hi.y = b2u(h1); hi.z = b2u(h2); hi.w = b2u(h3);
    lo.x = b2u(l0); lo.y = b2u(l1); lo.z = b2u(l2); lo.w = b2u(l3);
}

// ---------------- single conversion kernel (act + weights + counter zero) ----------------
#define CVT_ACT_B 2048          // BH/8/256
#define GW1 655360              // Wx groups (5120*1024/8)
#define GW2 1310720             // +Ux
#define GW3 1572864             // +a1
#define GWS 131072              // each H*H/8
#define CVT_TOT 10240           // 2048 + 8192

__global__ void __launch_bounds__(256)
cvt_all(const float4* __restrict__ x, const float4* __restrict__ h, const float4* __restrict__ ssg,
        const float4* __restrict__ Wx, const float4* __restrict__ Ux, const float4* __restrict__ a1,
        const float4* __restrict__ sw, const float4* __restrict__ r1,
        const float4* __restrict__ r2, const float4* __restrict__ r3,
        uint4* __restrict__ xh, uint4* __restrict__ xl,
        uint4* __restrict__ hh, uint4* __restrict__ hl,
        uint4* __restrict__ sgh, uint4* __restrict__ sgl,
        uint4* __restrict__ Wxh, uint4* __restrict__ Wxl,
        uint4* __restrict__ Uxh, uint4* __restrict__ Uxl,
        uint4* __restrict__ a1h, uint4* __restrict__ a1l,
        uint4* __restrict__ swh, uint4* __restrict__ swl,
        uint4* __restrict__ w1h, uint4* __restrict__ w1l,
        uint4* __restrict__ w2h, uint4* __restrict__ w2l,
        uint4* __restrict__ w3h, uint4* __restrict__ w3l)
{
    if (blockIdx.x == 0) g_cnt[threadIdx.x] = 0;      // zero counters each replay
    const int b = blockIdx.x;
    if (b < CVT_ACT_B) {
        int i = b * 256 + threadIdx.x;                // BH/8 groups
        float4 x0 = x[2*i], x1 = x[2*i+1];
        float4 h0 = h[2*i], h1 = h[2*i+1];
        float4 s0 = ssg[2*i], s1 = ssg[2*i+1];
        uint4 hi, lo;
        split8(x0, x1, hi, lo); xh[i] = hi; xl[i] = lo;
        split8(h0, h1, hi, lo); hh[i] = hi; hl[i] = lo;
        s0.x += h0.x; s0.y += h0.y; s0.z += h0.z; s0.w += h0.w;
        s1.x += h1.x; s1.y += h1.y; s1.z += h1.z; s1.w += h1.w;
        split8(s0, s1, hi, lo); sgh[i] = hi; sgl[i] = lo;
    } else {
        int i = (b - CVT_ACT_B) * 256 + threadIdx.x;
        const float4* src; uint4 *oh, *ol; int j;
        if      (i < GW1)          { src = Wx; oh = Wxh; ol = Wxl; j = i; }
        else if (i < GW2)          { src = Ux; oh = Uxh; ol = Uxl; j = i - GW1; }
        else if (i < GW3)          { src = a1; oh = a1h; ol = a1l; j = i - GW2; }
        else if (i < GW3 + GWS)    { src = sw; oh = swh; ol = swl; j = i - GW3; }
        else if (i < GW3 + 2*GWS)  { src = r1; oh = w1h; ol = w1l; j = i - GW3 - GWS; }
        else if (i < GW3 + 3*GWS)  { src = r2; oh = w2h; ol = w2l; j = i - GW3 - 2*GWS; }
        else                       { src = r3; oh = w3h; ol = w3l; j = i - GW3 - 3*GWS; }
        float4 v0 = src[2*j], v1 = src[2*j+1];
        uint4 hi, lo;
        split8(v0, v1, hi, lo);
        oh[j] = hi; ol[j] = lo;
    }
}

// ---------------- multi-GEMM descriptor ----------------
// modes: 0 fp32 out ; 1 relu fp32 ; 2 gate acts ; 3 r3+cell fused ; 4 relu + bf16 pair out
struct GemmDesc {
    const __nv_bfloat16 *A1h, *A1l, *W1h, *W1l;
    const __nv_bfloat16 *A2h, *A2l, *W2h, *W2l;
    const float *b1, *b2;
    float* Cf; __nv_bfloat16* Chi; __nv_bfloat16* Clo;
    int lda1, ldw1, lda2, ldw2;
    int s1, s2;          // number of K=16 chunks per operand pair
    int ldc, mode, nx;
};
struct DescPack {
    GemmDesc d[6];
    int starts[7];
};

// mega grid layout
#define ALPHA_B0 2048
#define ALPHA_B1 2080
#define MEGA_BLOCKS 2592

// ---------------- persistent dependency-graph mega GEMM kernel ----------------
__global__ void __launch_bounds__(256, 2)
mega(const __grid_constant__ DescPack P,
     const float* __restrict__ gates, const float* __restrict__ c_prev,
     float* __restrict__ alphav, const float* __restrict__ ssg,
     float* __restrict__ out_h, float* __restrict__ out_c,
     const float* __restrict__ ahbuf, const float* __restrict__ a2w,
     const float* __restrict__ a2b)
{
    extern __shared__ char smem[];
    const int tid = threadIdx.x;
    const int bid = blockIdx.x;

    // ---- alpha reduction blocks ----
    if (bid >= ALPHA_B0 && bid < ALPHA_B1) {
        const int mc = bid - ALPHA_B0;
        spin_wait(&g_cnt[32 + mc], 8);                // ah row-block complete
        const int l8 = tid & 7, r0 = tid >> 3;
#pragma unroll
        for (int p = 0; p < 4; ++p) {
            const int m = mc * 128 + p * 32 + r0;
            float s = 0.f;
            for (int k = l8; k < 1024; k += 8)
                s += ahbuf[(size_t)m * 1024 + k] * a2w[k];
            s += __shfl_down_sync(0xffffffffu, s, 4);
            s += __shfl_down_sync(0xffffffffu, s, 2);
            s += __shfl_down_sync(0xffffffffu, s, 1);
            if (l8 == 0) alphav[m] = 1.f / (1.f + __expf(-(s + a2b[0])));
        }
        signal_cnt(&g_cnt[128 + mc]);
        return;
    }

    const uint32_t sbase = smem_u32(smem);
    const int wid = tid >> 5, lane = tid & 31;
    const int wm = wid >> 2, wn = wid & 3;

    int t = bid, di = 0;
    while (di + 1 < 6 && t >= P.starts[di + 1]) ++di;
    const GemmDesc& d = P.d[di];
    const int rel = t - P.starts[di];
    const int m0 = (rel / d.nx) * 128, n0 = (rel % d.nx) * 128;
    const int rb = m0 >> 7;
    const int s1 = d.s1, S = d.s1 + d.s2;

    // mainloop input dependencies
    if (di == 4) spin_wait(&g_cnt[96 + rb], 8);       // r2 waits r1 row-block
    if (di == 5) spin_wait(&g_cnt[160 + rb], 8);      // r3 waits r2 row-block

    float acc[4][4][4];
#pragma unroll
    for (int a = 0; a < 4; ++a)
#pragma unroll
        for (int b = 0; b < 4; ++b)
#pragma unroll
            for (int q = 0; q < 4; ++q) acc[a][b][q] = 0.f;

    auto issue_load = [&](int s) {
        const __nv_bfloat16 *Ah, *Al, *Wh, *Wl; int lda, ldw, koff;
        if (s < s1) { Ah = d.A1h; Al = d.A1l; Wh = d.W1h; Wl = d.W1l; lda = d.lda1; ldw = d.ldw1; koff = s * 16; }
        else        { Ah = d.A2h; Al = d.A2l; Wh = d.W2h; Wl = d.W2l; lda = d.lda2; ldw = d.ldw2; koff = (s - s1) * 16; }
        const __nv_bfloat16* srcs[4] = {Ah, Al, Wh, Wl};
        uint32_t dst0 = sbase + (uint32_t)(s & (NSTAGE - 1)) * STG_BYTES;
#pragma unroll
        for (int i = 0; i < 4; ++i) {                 // 1024 16B chunks (4 arrays x 128 rows x 2)
            int idx = tid + i * 256;
            int arr = idx >> 8, r = (idx & 255) >> 1, c = idx & 1;
            int ldx = (arr < 2) ? lda : ldw;
            int rbase = (arr < 2) ? m0 : n0;
            const __nv_bfloat16* g = srcs[arr] + (size_t)(rbase + r) * ldx + koff + c * 8;
            uint32_t dsta = dst0 + arr * ARR_BYTES + r * (RS * 2) + c * 16;
            CP_ASYNC16(dsta, g);
        }
        CP_COMMIT();
    };

    issue_load(0); issue_load(1); issue_load(2);

    for (int s = 0; s < S; ++s) {
        // guarantee stage s's group complete
        if (s + 2 < S)      CP_WAIT(2);
        else if (s + 1 < S) CP_WAIT(1);
        else                CP_WAIT(0);
        __syncthreads();                 // all warps done compute(s-1); stage-s loads visible
        if (s + 3 < S) issue_load(s + 3);  // writes buf (s-1)&3, proven free by the barrier

        uint32_t SB = sbase + (uint32_t)(s & (NSTAGE - 1)) * STG_BYTES;
        uint32_t Ahb = SB, Alb = SB + ARR_BYTES;
        uint32_t Whb = SB + 2 * ARR_BYTES, Wlb = SB + 3 * ARR_BYTES;

        // B fragments: 4 n-blocks at this K=16
        uint32_t bh[4][2], bl[4][2];
        {
            const int g = lane >> 3;
            const int rbw = wn * 32 + ((g >> 1) << 3) + (lane & 7);
            const int cb = (g & 1) << 3;
#pragma unroll
            for (int p = 0; p < 2; ++p) {
                uint32_t off = (uint32_t)((rbw + p * 16) * RS + cb) * 2;
                ldsm4(bh[2*p][0], bh[2*p][1], bh[2*p+1][0], bh[2*p+1][1], Whb + off);
                ldsm4(bl[2*p][0], bl[2*p][1], bl[2*p+1][0], bl[2*p+1][1], Wlb + off);
            }
        }
        const int ra = wm * 64 + (lane & 15);
        const int ca = (lane >> 4) << 3;
        uint32_t ah[2][4], al[2][4];
        {
            uint32_t off0 = (uint32_t)(ra * RS + ca) * 2;
            ldsm4(ah[0][0], ah[0][1], ah[0][2], ah[0][3], Ahb + off0);
            ldsm4(al[0][0], al[0][1], al[0][2], al[0][3], Alb + off0);
        }
#pragma unroll
        for (int mb = 0; mb < 4; ++mb) {
            const int cur = mb & 1, nxt = cur ^ 1;
            if (mb < 3) {
                uint32_t off = (uint32_t)((ra + (mb + 1) * 16) * RS + ca) * 2;
                ldsm4(ah[nxt][0], ah[nxt][1], ah[nxt][2], ah[nxt][3], Ahb + off);
                ldsm4(al[nxt][0], al[nxt][1], al[nxt][2], al[nxt][3], Alb + off);
            }
#pragma unroll
            for (int nb = 0; nb < 4; ++nb) mma16816(acc[mb][nb], ah[cur], bh[nb]);
#pragma unroll
            for (int nb = 0; nb < 4; ++nb) mma16816(acc[mb][nb], ah[cur], bl[nb]);
#pragma unroll
            for (int nb = 0; nb < 4; ++nb) mma16816(acc[mb][nb], al[cur], bh[nb]);
        }
        // no bottom barrier: next iteration's top barrier covers the WAR on buf (s)&3
    }

    // r3 epilogue dependencies (deferred past mainloop for overlap)
    if (di == 5) {
        spin_wait(&g_cnt[0 + rb], 40);    // gates row-block
        spin_wait(&g_cnt[64 + rb], 8);    // ssg row-block
        spin_wait(&g_cnt[128 + rb], 1);   // alpha chunk
    }

    // ---------------- epilogue ----------------
    const int mode = d.mode;
#pragma unroll
    for (int mb = 0; mb < 4; ++mb) {
#pragma unroll
        for (int nb = 0; nb < 4; ++nb) {
#pragma unroll
            for (int h = 0; h < 2; ++h) {
                const int m = m0 + wm * 64 + mb * 16 + (lane >> 2) + h * 8;
                const int n = n0 + wn * 32 + nb * 8 + 2 * (lane & 3);
                float v0 = acc[mb][nb][2 * h]     + d.b1[n];
                float v1 = acc[mb][nb][2 * h + 1] + d.b1[n + 1];
                if (d.b2) { v0 += d.b2[n]; v1 += d.b2[n + 1]; }
                if (mode == 1 || mode == 4) { v0 = fmaxf(v0, 0.f); v1 = fmaxf(v1, 0.f); }
                if (mode == 2) {
                    const int g = n >> 10;
                    if (g == 3) { v0 = tanh_fast(v0); v1 = tanh_fast(v1); }
                    else { v0 = 1.f / (1.f + __expf(-v0)); v1 = 1.f / (1.f + __expf(-v1)); }
                }
                const size_t gm = (size_t)m * d.ldc + n;
                if (mode == 4) {
                    __nv_bfloat162 hi2, lo2;
                    split2(v0, v1, hi2, lo2);
                    *(__nv_bfloat162*)(d.Chi + gm) = hi2;
                    *(__nv_bfloat162*)(d.Clo + gm) = lo2;
                } else if (mode == 3) {
                    const size_t gb = (size_t)m * NG + n;
                    const float a = alphav[m];
                    float2 cp = *(const float2*)(c_prev + gm);
                    float2 sg = *(const float2*)(ssg + gm);
                    float c0 = gates[gb + 1024] * cp.x
                             + gates[gb] * gates[gb + 3072] * gates[gb + 4096] * a * sg.x + v0;
                    float c1 = gates[gb + 1025] * cp.y
                             + gates[gb + 1] * gates[gb + 3073] * gates[gb + 4097] * a * sg.y + v1;
                    float2 oc; oc.x = c0; oc.y = c1;
                    float2 oh; oh.x = gates[gb + 2048] * tanh_fast(c0);
                    oh.y = gates[gb + 2049] * tanh_fast(c1);
                    *(float2*)(out_c + gm) = oc;
                    *(float2*)(out_h + gm) = oh;
                } else {
                    float2 o; o.x = v0; o.y = v1;
                    *(float2*)(d.Cf + gm) = o;
                }
            }
        }
    }

    // completion signals
    if      (di == 0) signal_cnt(&g_cnt[0 + rb]);
    else if (di == 1) signal_cnt(&g_cnt[32 + rb]);
    else if (di == 2) signal_cnt(&g_cnt[64 + rb]);
    else if (di == 3) signal_cnt(&g_cnt[96 + rb]);
    else if (di == 4) signal_cnt(&g_cnt[160 + rb]);
}

// ---------------- launch ----------------
extern "C" void kernel_launch(void* const* d_in, const int* in_sizes, int n_in,
                              void* d_out, int out_size)
{
    const float* x      = (const float*)d_in[0];
    const float* h_prev = (const float*)d_in[1];
    const float* c_prev = (const float*)d_in[2];
    const float* ssg_st = (const float*)d_in[3];
    const float* Wx     = (const float*)d_in[4];
    const float* bWx    = (const float*)d_in[5];
    const float* Ux     = (const float*)d_in[6];
    const float* bUx    = (const float*)d_in[7];
    const float* a1_w   = (const float*)d_in[8];
    const float* a1_b   = (const float*)d_in[9];
    const float* a2_w   = (const float*)d_in[10];
    const float* a2_b   = (const float*)d_in[11];
    const float* r1_w   = (const float*)d_in[12];
    const float* r1_b   = (const float*)d_in[13];
    const float* r2_w   = (const float*)d_in[14];
    const float* r2_b   = (const float*)d_in[15];
    const float* r3_w   = (const float*)d_in[16];
    const float* r3_b   = (const float*)d_in[17];
    const float* ssg_w  = (const float*)d_in[18];
    const float* ssg_b  = (const float*)d_in[19];

    float* out = (float*)d_out;
    float* out_h   = out;
    float* out_c   = out + (size_t)BH;
    float* out_ssg = out + 2 * (size_t)BH;

    __nv_bfloat16 *xh, *xl, *hh, *hl, *sgh, *sgl, *r1h, *r1l, *r2h, *r2l;
    __nv_bfloat16 *Wxh, *Wxl, *Uxh, *Uxl, *a1h, *a1l, *swh, *swl, *w1h, *w1l, *w2h, *w2l, *w3h, *w3l;
    float *gates, *ah, *alpha;
    cudaGetSymbolAddress((void**)&xh, s_x_hi);   cudaGetSymbolAddress((void**)&xl, s_x_lo);
    cudaGetSymbolAddress((void**)&hh, s_h_hi);   cudaGetSymbolAddress((void**)&hl, s_h_lo);
    cudaGetSymbolAddress((void**)&sgh, s_sg_hi); cudaGetSymbolAddress((void**)&sgl, s_sg_lo);
    cudaGetSymbolAddress((void**)&r1h, s_r1_hi); cudaGetSymbolAddress((void**)&r1l, s_r1_lo);
    cudaGetSymbolAddress((void**)&r2h, s_r2_hi); cudaGetSymbolAddress((void**)&r2l, s_r2_lo);
    cudaGetSymbolAddress((void**)&Wxh, w_Wx_hi); cudaGetSymbolAddress((void**)&Wxl, w_Wx_lo);
    cudaGetSymbolAddress((void**)&Uxh, w_Ux_hi); cudaGetSymbolAddress((void**)&Uxl, w_Ux_lo);
    cudaGetSymbolAddress((void**)&a1h, w_a1_hi); cudaGetSymbolAddress((void**)&a1l, w_a1_lo);
    cudaGetSymbolAddress((void**)&swh, w_sw_hi); cudaGetSymbolAddress((void**)&swl, w_sw_lo);
    cudaGetSymbolAddress((void**)&w1h, w_r1_hi); cudaGetSymbolAddress((void**)&w1l, w_r1_lo);
    cudaGetSymbolAddress((void**)&w2h, w_r2_hi); cudaGetSymbolAddress((void**)&w2l, w_r2_lo);
    cudaGetSymbolAddress((void**)&w3h, w_r3_hi); cudaGetSymbolAddress((void**)&w3l, w_r3_lo);
    cudaGetSymbolAddress((void**)&gates, g_gates);
    cudaGetSymbolAddress((void**)&ah, g_ah);
    cudaGetSymbolAddress((void**)&alpha, g_alpha);

    cudaFuncSetAttribute(mega, cudaFuncAttributeMaxDynamicSharedMemorySize, SMEM_BYTES);

    const dim3 blk(256);

    // launch 1: all conversions + counter zeroing
    cvt_all<<<CVT_TOT, blk>>>((const float4*)x, (const float4*)h_prev, (const float4*)ssg_st,
                              (const float4*)Wx, (const float4*)Ux, (const float4*)a1_w,
                              (const float4*)ssg_w, (const float4*)r1_w,
                              (const float4*)r2_w, (const float4*)r3_w,
                              (uint4*)xh, (uint4*)xl, (uint4*)hh, (uint4*)hl,
                              (uint4*)sgh, (uint4*)sgl,
                              (uint4*)Wxh, (uint4*)Wxl, (uint4*)Uxh, (uint4*)Uxl,
                              (uint4*)a1h, (uint4*)a1l, (uint4*)swh, (uint4*)swl,
                              (uint4*)w1h, (uint4*)w1l, (uint4*)w2h, (uint4*)w2l,
                              (uint4*)w3h, (uint4*)w3l);

    // launch 2: mega dependency-graph GEMM schedule (s1/s2 in K16 chunks)
    DescPack P = {};
    P.d[0] = { xh, xl, Wxh, Wxl, hh, hl, Uxh, Uxl, bWx, bUx,
               gates, nullptr, nullptr, 1024, 1024, 1024, 1024, 64, 64, NG, 2, NG/128 };
    P.d[1] = { xh, xl, a1h, a1l, hh, hl, a1h + 1024, a1l + 1024, a1_b, nullptr,
               ah, nullptr, nullptr, 1024, 2048, 1024, 2048, 64, 64, HH, 1, HH/128 };
    P.d[2] = { sgh, sgl, swh, swl, nullptr, nullptr, nullptr, nullptr, ssg_b, nullptr,
               out_ssg, nullptr, nullptr, 1024, 1024, 0, 0, 64, 0, HH, 0, HH/128 };
    P.d[3] = { hh, hl, w1h, w1l, nullptr, nullptr, nullptr, nullptr, r1_b, nullptr,
               nullptr, r1h, r1l, 1024, 1024, 0, 0, 64, 0, HH, 4, HH/128 };
    P.d[4] = { r1h, r1l, w2h, w2l, nullptr, nullptr, nullptr, nullptr, r2_b, nullptr,
               nullptr, r2h, r2l, 1024, 1024, 0, 0, 64, 0, HH, 4, HH/128 };
    P.d[5] = { r2h, r2l, w3h, w3l, nullptr, nullptr, nullptr, nullptr, r3_b, nullptr,
               nullptr, nullptr, nullptr, 1024, 1024, 0, 0, 64, 0, HH, 3, HH/128 };
    P.starts[0] = 0;    P.starts[1] = 1280; P.starts[2] = 1536; P.starts[3] = 1792;
    P.starts[4] = 2080; P.starts[5] = 2336; P.starts[6] = 2592;

    mega<<<MEGA_BLOCKS, blk, SMEM_BYTES>>>(P, gates, c_prev, alpha, out_ssg,
                                           out_h, out_c, ah, a2_w, a2_b);
}

// round 14
// speedup vs baseline: 1.2019x; 1.2019x over previous
#include <cuda_runtime.h>
#include <cuda_bf16.h>
#include <math.h>
#include <stdint.h>

#define BB 4096
#define HH 1024
#define NG 5120
#define BH (4096*1024)

// GEMM tiling: CTA 128x128, 8 warps (2x4), warp 64x32, K-step 32, 2-stage, 2 CTAs/SM
// single __syncthreads per stage (issue moved after the barrier covers the WAR)
#define RS 40                        // padded smem row stride (bf16) = 80B
#define ARR_BYTES (128*RS*2)         // 10240 per tile array
#define STG_BYTES (4*ARR_BYTES)      // 40960 per stage (Ah,Al,Wh,Wl)
#define SMEM_BYTES (2*STG_BYTES)     // 81920 double-buffered

// ---------------- scratch (device globals; no allocs) ----------------
__device__ __nv_bfloat16 s_x_hi[(size_t)BB*HH],  s_x_lo[(size_t)BB*HH];
__device__ __nv_bfloat16 s_h_hi[(size_t)BB*HH],  s_h_lo[(size_t)BB*HH];
__device__ __nv_bfloat16 s_sg_hi[(size_t)BB*HH], s_sg_lo[(size_t)BB*HH];
__device__ __nv_bfloat16 s_r1_hi[(size_t)BB*HH], s_r1_lo[(size_t)BB*HH];
__device__ __nv_bfloat16 s_r2_hi[(size_t)BB*HH], s_r2_lo[(size_t)BB*HH];
__device__ __nv_bfloat16 w_Wx_hi[(size_t)NG*HH], w_Wx_lo[(size_t)NG*HH];
__device__ __nv_bfloat16 w_Ux_hi[(size_t)NG*HH], w_Ux_lo[(size_t)NG*HH];
__device__ __nv_bfloat16 w_a1_hi[(size_t)HH*2048], w_a1_lo[(size_t)HH*2048];
__device__ __nv_bfloat16 w_sw_hi[(size_t)HH*HH], w_sw_lo[(size_t)HH*HH];
__device__ __nv_bfloat16 w_r1_hi[(size_t)HH*HH], w_r1_lo[(size_t)HH*HH];
__device__ __nv_bfloat16 w_r2_hi[(size_t)HH*HH], w_r2_lo[(size_t)HH*HH];
__device__ __nv_bfloat16 w_r3_hi[(size_t)HH*HH], w_r3_lo[(size_t)HH*HH];
__device__ float g_gates[(size_t)BB*NG];
__device__ float g_ah[(size_t)BB*HH];
__device__ float g_alpha[BB];
// sync counters: [0..32) gates_rb  [32..64) ah_rb  [64..96) ssg_rb
//                [96..128) r1_rb   [128..160) alpha_ch  [160..192) r2_rb
__device__ int g_cnt[256];

// ---------------- helpers ----------------
__device__ __forceinline__ uint32_t smem_u32(const void* p) {
    uint32_t a;
    asm("{ .reg .u64 t; cvta.to.shared.u64 t, %1; cvt.u32.u64 %0, t; }" : "=r"(a) : "l"(p));
    return a;
}
__device__ __forceinline__ void ldsm4(uint32_t& r0, uint32_t& r1, uint32_t& r2, uint32_t& r3, uint32_t a) {
    asm volatile("ldmatrix.sync.aligned.m8n8.x4.shared.b16 {%0,%1,%2,%3}, [%4];"
        : "=r"(r0), "=r"(r1), "=r"(r2), "=r"(r3) : "r"(a));
}
__device__ __forceinline__ void mma16816(float* c, const uint32_t* a, const uint32_t* b) {
    asm volatile("mma.sync.aligned.m16n8k16.row.col.f32.bf16.bf16.f32 "
        "{%0,%1,%2,%3}, {%4,%5,%6,%7}, {%8,%9}, {%0,%1,%2,%3};"
        : "+f"(c[0]), "+f"(c[1]), "+f"(c[2]), "+f"(c[3])
        : "r"(a[0]), "r"(a[1]), "r"(a[2]), "r"(a[3]), "r"(b[0]), "r"(b[1]));
}
#define CP_ASYNC16(dst, src) \
    asm volatile("cp.async.cg.shared.global [%0], [%1], 16;" :: "r"(dst), "l"(src))
#define CP_COMMIT()  asm volatile("cp.async.commit_group;" ::: "memory")
#define CP_WAIT(n)   asm volatile("cp.async.wait_group %0;" :: "n"(n) : "memory")

__device__ __forceinline__ int ld_acq(const int* p) {
    int v; asm volatile("ld.acquire.gpu.global.s32 %0, [%1];" : "=r"(v) : "l"(p) : "memory");
    return v;
}
__device__ __forceinline__ void spin_wait(const int* c, int target) {
    if (threadIdx.x == 0) {
        while (ld_acq(c) < target) __nanosleep(128);
    }
    __syncthreads();
}
__device__ __forceinline__ void signal_cnt(int* c) {
    __threadfence();
    __syncthreads();
    if (threadIdx.x == 0) atomicAdd(c, 1);
}

__device__ __forceinline__ float tanh_fast(float v) {
    return 2.f / (1.f + __expf(-2.f * v)) - 1.f;
}

__device__ __forceinline__ void split2(float v0, float v1, __nv_bfloat162& hi, __nv_bfloat162& lo) {
    __nv_bfloat16 h0 = __float2bfloat16_rn(v0), h1 = __float2bfloat16_rn(v1);
    __nv_bfloat16 l0 = __float2bfloat16_rn(v0 - __bfloat162float(h0));
    __nv_bfloat16 l1 = __float2bfloat16_rn(v1 - __bfloat162float(h1));
    hi = __nv_bfloat162(h0, h1); lo = __nv_bfloat162(l0, l1);
}
__device__ __forceinline__ uint32_t b2u(__nv_bfloat162 v) {
    uint32_t u; *(__nv_bfloat162*)&u = v; return u;
}
// 8 floats -> 16B hi + 16B lo, paired bf16x2 conversions
__device__ __forceinline__ void split8(float4 a, float4 b, uint4& hi, uint4& lo) {
    float2 a01 = make_float2(a.x, a.y), a23 = make_float2(a.z, a.w);
    float2 b01 = make_float2(b.x, b.y), b23 = make_float2(b.z, b.w);
    __nv_bfloat162 h0 = __float22bfloat162_rn(a01);
    __nv_bfloat162 h1 = __float22bfloat162_rn(a23);
    __nv_bfloat162 h2 = __float22bfloat162_rn(b01);
    __nv_bfloat162 h3 = __float22bfloat162_rn(b23);
    float2 f0 = __bfloat1622float2(h0), f1 = __bfloat1622float2(h1);
    float2 f2 = __bfloat1622float2(h2), f3 = __bfloat1622float2(h3);
    __nv_bfloat162 l0 = __float22bfloat162_rn(make_float2(a01.x - f0.x, a01.y - f0.y));
    __nv_bfloat162 l1 = __float22bfloat162_rn(make_float2(a23.x - f1.x, a23.y - f1.y));
    __nv_bfloat162 l2 = __float22bfloat162_rn(make_float2(b01.x - f2.x, b01.y - f2.y));
    __nv_bfloat162 l3 = __float22bfloat162_rn(make_float2(b23.x - f3.x, b23.y - f3.y));
    hi.x = b2u(h0); hi.y = b2u(h1); hi.z = b2u(h2); hi.w = b2u(h3);
    lo.x = b2u(l0); lo.y = b2u(l1); lo.z = b2u(l2); lo.w = b2u(l3);
}

// ---------------- single conversion kernel (act + weights + counter zero) ----------------
#define CVT_ACT_B 2048          // BH/8/256
#define GW1 655360              // Wx groups (5120*1024/8)
#define GW2 1310720             // +Ux
#define GW3 1572864             // +a1
#define GWS 131072              // each H*H/8
#define CVT_TOT 10240           // 2048 + 8192

__global__ void __launch_bounds__(256)
cvt_all(const float4* __restrict__ x, const float4* __restrict__ h, const float4* __restrict__ ssg,
        const float4* __restrict__ Wx, const float4* __restrict__ Ux, const float4* __restrict__ a1,
        const float4* __restrict__ sw, const float4* __restrict__ r1,
        const float4* __restrict__ r2, const float4* __restrict__ r3,
        uint4* __restrict__ xh, uint4* __restrict__ xl,
        uint4* __restrict__ hh, uint4* __restrict__ hl,
        uint4* __restrict__ sgh, uint4* __restrict__ sgl,
        uint4* __restrict__ Wxh, uint4* __restrict__ Wxl,
        uint4* __restrict__ Uxh, uint4* __restrict__ Uxl,
        uint4* __restrict__ a1h, uint4* __restrict__ a1l,
        uint4* __restrict__ swh, uint4* __restrict__ swl,
        uint4* __restrict__ w1h, uint4* __restrict__ w1l,
        uint4* __restrict__ w2h, uint4* __restrict__ w2l,
        uint4* __restrict__ w3h, uint4* __restrict__ w3l)
{
    if (blockIdx.x == 0) g_cnt[threadIdx.x] = 0;      // zero counters each replay
    const int b = blockIdx.x;
    if (b < CVT_ACT_B) {
        int i = b * 256 + threadIdx.x;                // BH/8 groups
        float4 x0 = x[2*i], x1 = x[2*i+1];
        float4 h0 = h[2*i], h1 = h[2*i+1];
        float4 s0 = ssg[2*i], s1 = ssg[2*i+1];
        uint4 hi, lo;
        split8(x0, x1, hi, lo); xh[i] = hi; xl[i] = lo;
        split8(h0, h1, hi, lo); hh[i] = hi; hl[i] = lo;
        s0.x += h0.x; s0.y += h0.y; s0.z += h0.z; s0.w += h0.w;
        s1.x += h1.x; s1.y += h1.y; s1.z += h1.z; s1.w += h1.w;
        split8(s0, s1, hi, lo); sgh[i] = hi; sgl[i] = lo;
    } else {
        int i = (b - CVT_ACT_B) * 256 + threadIdx.x;
        const float4* src; uint4 *oh, *ol; int j;
        if      (i < GW1)          { src = Wx; oh = Wxh; ol = Wxl; j = i; }
        else if (i < GW2)          { src = Ux; oh = Uxh; ol = Uxl; j = i - GW1; }
        else if (i < GW3)          { src = a1; oh = a1h; ol = a1l; j = i - GW2; }
        else if (i < GW3 + GWS)    { src = sw; oh = swh; ol = swl; j = i - GW3; }
        else if (i < GW3 + 2*GWS)  { src = r1; oh = w1h; ol = w1l; j = i - GW3 - GWS; }
        else if (i < GW3 + 3*GWS)  { src = r2; oh = w2h; ol = w2l; j = i - GW3 - 2*GWS; }
        else                       { src = r3; oh = w3h; ol = w3l; j = i - GW3 - 3*GWS; }
        float4 v0 = src[2*j], v1 = src[2*j+1];
        uint4 hi, lo;
        split8(v0, v1, hi, lo);
        oh[j] = hi; ol[j] = lo;
    }
}

// ---------------- multi-GEMM descriptor ----------------
// modes: 0 fp32 out ; 1 relu fp32 ; 2 gate acts ; 3 r3+cell fused ; 4 relu + bf16 pair out
struct GemmDesc {
    const __nv_bfloat16 *A1h, *A1l, *W1h, *W1l;
    const __nv_bfloat16 *A2h, *A2l, *W2h, *W2l;
    const float *b1, *b2;
    float* Cf; __nv_bfloat16* Chi; __nv_bfloat16* Clo;
    int lda1, ldw1, lda2, ldw2;
    int s1, s2;          // number of K=32 chunks per operand pair
    int ldc, mode, nx;
};
struct DescPack {
    GemmDesc d[6];
    int starts[7];
};

// mega grid layout
#define ALPHA_B0 2048
#define ALPHA_B1 2080
#define MEGA_BLOCKS 2592

// ---------------- persistent dependency-graph mega GEMM kernel ----------------
__global__ void __launch_bounds__(256, 2)
mega(const __grid_constant__ DescPack P,
     const float* __restrict__ gates, const float* __restrict__ c_prev,
     float* __restrict__ alphav, const float* __restrict__ ssg,
     float* __restrict__ out_h, float* __restrict__ out_c,
     const float* __restrict__ ahbuf, const float* __restrict__ a2w,
     const float* __restrict__ a2b)
{
    extern __shared__ char smem[];
    const int tid = threadIdx.x;
    const int bid = blockIdx.x;

    // ---- alpha reduction blocks ----
    if (bid >= ALPHA_B0 && bid < ALPHA_B1) {
        const int mc = bid - ALPHA_B0;
        spin_wait(&g_cnt[32 + mc], 8);                // ah row-block complete
        const int l8 = tid & 7, r0 = tid >> 3;
#pragma unroll
        for (int p = 0; p < 4; ++p) {
            const int m = mc * 128 + p * 32 + r0;
            float s = 0.f;
            for (int k = l8; k < 1024; k += 8)
                s += ahbuf[(size_t)m * 1024 + k] * a2w[k];
            s += __shfl_down_sync(0xffffffffu, s, 4);
            s += __shfl_down_sync(0xffffffffu, s, 2);
            s += __shfl_down_sync(0xffffffffu, s, 1);
            if (l8 == 0) alphav[m] = 1.f / (1.f + __expf(-(s + a2b[0])));
        }
        signal_cnt(&g_cnt[128 + mc]);
        return;
    }

    const uint32_t sbase = smem_u32(smem);
    const int wid = tid >> 5, lane = tid & 31;
    const int wm = wid >> 2, wn = wid & 3;

    int t = bid, di = 0;
    while (di + 1 < 6 && t >= P.starts[di + 1]) ++di;
    const GemmDesc& d = P.d[di];
    const int rel = t - P.starts[di];
    const int m0 = (rel / d.nx) * 128, n0 = (rel % d.nx) * 128;
    const int rb = m0 >> 7;
    const int s1 = d.s1, S = d.s1 + d.s2;

    // mainloop input dependencies
    if (di == 4) spin_wait(&g_cnt[96 + rb], 8);       // r2 waits r1 row-block
    if (di == 5) spin_wait(&g_cnt[160 + rb], 8);      // r3 waits r2 row-block

    float acc[4][4][4];
#pragma unroll
    for (int a = 0; a < 4; ++a)
#pragma unroll
        for (int b = 0; b < 4; ++b)
#pragma unroll
            for (int q = 0; q < 4; ++q) acc[a][b][q] = 0.f;

    auto issue_load = [&](int s) {
        const __nv_bfloat16 *Ah, *Al, *Wh, *Wl; int lda, ldw, koff;
        if (s < s1) { Ah = d.A1h; Al = d.A1l; Wh = d.W1h; Wl = d.W1l; lda = d.lda1; ldw = d.ldw1; koff = s * 32; }
        else        { Ah = d.A2h; Al = d.A2l; Wh = d.W2h; Wl = d.W2l; lda = d.lda2; ldw = d.ldw2; koff = (s - s1) * 32; }
        const __nv_bfloat16* srcs[4] = {Ah, Al, Wh, Wl};
        uint32_t dst0 = sbase + (uint32_t)(s & 1) * STG_BYTES;
#pragma unroll
        for (int arr = 0; arr < 4; ++arr) {
            const __nv_bfloat16* src = srcs[arr];
            int ldx = (arr < 2) ? lda : ldw;
#pragma unroll
            for (int i = 0; i < 2; ++i) {
                int idx = tid + i * 256;
                int row = idx >> 2, c = idx & 3;
                int rbase = (arr < 2) ? m0 : n0;
                const __nv_bfloat16* g = src + (size_t)(rbase + row) * ldx + koff + c * 8;
                uint32_t dsta = dst0 + arr * ARR_BYTES + row * 80 + c * 16;
                CP_ASYNC16(dsta, g);
            }
        }
        CP_COMMIT();
    };

    issue_load(0);

    for (int s = 0; s < S; ++s) {
        CP_WAIT(0);              // only group s is in flight here; wait for it
        __syncthreads();         // all warps done compute(s-1) -> buf (s+1)&1 free; stage-s data visible
        if (s + 1 < S) issue_load(s + 1);

        uint32_t SB = sbase + (uint32_t)(s & 1) * STG_BYTES;
        uint32_t Ahb = SB, Alb = SB + ARR_BYTES;
        uint32_t Whb = SB + 2 * ARR_BYTES, Wlb = SB + 3 * ARR_BYTES;

#pragma unroll
        for (int k16 = 0; k16 < 2; ++k16) {
            const int k0 = k16 * 16;
            uint32_t bh[4][2], bl[4][2];
            {
                const int g = lane >> 3;
                const int rbw = wn * 32 + ((g >> 1) << 3) + (lane & 7);
                const int cb = k0 + ((g & 1) << 3);
#pragma unroll
                for (int p = 0; p < 2; ++p) {
                    uint32_t off = (uint32_t)((rbw + p * 16) * RS + cb) * 2;
                    ldsm4(bh[2*p][0], bh[2*p][1], bh[2*p+1][0], bh[2*p+1][1], Whb + off);
                    ldsm4(bl[2*p][0], bl[2*p][1], bl[2*p+1][0], bl[2*p+1][1], Wlb + off);
                }
            }
            const int ra = wm * 64 + (lane & 15);
            const int ca = k0 + ((lane >> 4) << 3);
            uint32_t ah[2][4], al[2][4];
            {
                uint32_t off0 = (uint32_t)(ra * RS + ca) * 2;
                ldsm4(ah[0][0], ah[0][1], ah[0][2], ah[0][3], Ahb + off0);
                ldsm4(al[0][0], al[0][1], al[0][2], al[0][3], Alb + off0);
            }
#pragma unroll
            for (int mb = 0; mb < 4; ++mb) {
                const int cur = mb & 1, nxt = cur ^ 1;
                if (mb < 3) {
                    uint32_t off = (uint32_t)((ra + (mb + 1) * 16) * RS + ca) * 2;
                    ldsm4(ah[nxt][0], ah[nxt][1], ah[nxt][2], ah[nxt][3], Ahb + off);
                    ldsm4(al[nxt][0], al[nxt][1], al[nxt][2], al[nxt][3], Alb + off);
                }
#pragma unroll
                for (int nb = 0; nb < 4; ++nb) mma16816(acc[mb][nb], ah[cur], bh[nb]);
#pragma unroll
                for (int nb = 0; nb < 4; ++nb) mma16816(acc[mb][nb], ah[cur], bl[nb]);
#pragma unroll
                for (int nb = 0; nb < 4; ++nb) mma16816(acc[mb][nb], al[cur], bh[nb]);
            }
        }
        // no bottom barrier: next iteration's top barrier covers the WAR on buf s&1
    }

    // r3 epilogue dependencies (deferred past mainloop for overlap)
    if (di == 5) {
        spin_wait(&g_cnt[0 + rb], 40);    // gates row-block
        spin_wait(&g_cnt[64 + rb], 8);    // ssg row-block
        spin_wait(&g_cnt[128 + rb], 1);   // alpha chunk
    }

    // ---------------- epilogue ----------------
    const int mode = d.mode;
#pragma unroll
    for (int mb = 0; mb < 4; ++mb) {
#pragma unroll
        for (int nb = 0; nb < 4; ++nb) {
#pragma unroll
            for (int h = 0; h < 2; ++h) {
                const int m = m0 + wm * 64 + mb * 16 + (lane >> 2) + h * 8;
                const int n = n0 + wn * 32 + nb * 8 + 2 * (lane & 3);
                float v0 = acc[mb][nb][2 * h]     + d.b1[n];
                float v1 = acc[mb][nb][2 * h + 1] + d.b1[n + 1];
                if (d.b2) { v0 += d.b2[n]; v1 += d.b2[n + 1]; }
                if (mode == 1 || mode == 4) { v0 = fmaxf(v0, 0.f); v1 = fmaxf(v1, 0.f); }
                if (mode == 2) {
                    const int g = n >> 10;
                    if (g == 3) { v0 = tanh_fast(v0); v1 = tanh_fast(v1); }
                    else { v0 = 1.f / (1.f + __expf(-v0)); v1 = 1.f / (1.f + __expf(-v1)); }
                }
                const size_t gm = (size_t)m * d.ldc + n;
                if (mode == 4) {
                    __nv_bfloat162 hi2, lo2;
                    split2(v0, v1, hi2, lo2);
                    *(__nv_bfloat162*)(d.Chi + gm) = hi2;
                    *(__nv_bfloat162*)(d.Clo + gm) = lo2;
                } else if (mode == 3) {
                    const size_t gb = (size_t)m * NG + n;
                    const float a = alphav[m];
                    float2 cp = *(const float2*)(c_prev + gm);
                    float2 sg = *(const float2*)(ssg + gm);
                    float c0 = gates[gb + 1024] * cp.x
                             + gates[gb] * gates[gb + 3072] * gates[gb + 4096] * a * sg.x + v0;
                    float c1 = gates[gb + 1025] * cp.y
                             + gates[gb + 1] * gates[gb + 3073] * gates[gb + 4097] * a * sg.y + v1;
                    float2 oc; oc.x = c0; oc.y = c1;
                    float2 oh; oh.x = gates[gb + 2048] * tanh_fast(c0);
                    oh.y = gates[gb + 2049] * tanh_fast(c1);
                    *(float2*)(out_c + gm) = oc;
                    *(float2*)(out_h + gm) = oh;
                } else {
                    float2 o; o.x = v0; o.y = v1;
                    *(float2*)(d.Cf + gm) = o;
                }
            }
        }
    }

    // completion signals
    if      (di == 0) signal_cnt(&g_cnt[0 + rb]);
    else if (di == 1) signal_cnt(&g_cnt[32 + rb]);
    else if (di == 2) signal_cnt(&g_cnt[64 + rb]);
    else if (di == 3) signal_cnt(&g_cnt[96 + rb]);
    else if (di == 4) signal_cnt(&g_cnt[160 + rb]);
}

// ---------------- launch ----------------
extern "C" void kernel_launch(void* const* d_in, const int* in_sizes, int n_in,
                              void* d_out, int out_size)
{
    const float* x      = (const float*)d_in[0];
    const float* h_prev = (const float*)d_in[1];
    const float* c_prev = (const float*)d_in[2];
    const float* ssg_st = (const float*)d_in[3];
    const float* Wx     = (const float*)d_in[4];
    const float* bWx    = (const float*)d_in[5];
    const float* Ux     = (const float*)d_in[6];
    const float* bUx    = (const float*)d_in[7];
    const float* a1_w   = (const float*)d_in[8];
    const float* a1_b   = (const float*)d_in[9];
    const float* a2_w   = (const float*)d_in[10];
    const float* a2_b   = (const float*)d_in[11];
    const float* r1_w   = (const float*)d_in[12];
    const float* r1_b   = (const float*)d_in[13];
    const float* r2_w   = (const float*)d_in[14];
    const float* r2_b   = (const float*)d_in[15];
    const float* r3_w   = (const float*)d_in[16];
    const float* r3_b   = (const float*)d_in[17];
    const float* ssg_w  = (const float*)d_in[18];
    const float* ssg_b  = (const float*)d_in[19];

    float* out = (float*)d_out;
    float* out_h   = out;
    float* out_c   = out + (size_t)BH;
    float* out_ssg = out + 2 * (size_t)BH;

    __nv_bfloat16 *xh, *xl, *hh, *hl, *sgh, *sgl, *r1h, *r1l, *r2h, *r2l;
    __nv_bfloat16 *Wxh, *Wxl, *Uxh, *Uxl, *a1h, *a1l, *swh, *swl, *w1h, *w1l, *w2h, *w2l, *w3h, *w3l;
    float *gates, *ah, *alpha;
    cudaGetSymbolAddress((void**)&xh, s_x_hi);   cudaGetSymbolAddress((void**)&xl, s_x_lo);
    cudaGetSymbolAddress((void**)&hh, s_h_hi);   cudaGetSymbolAddress((void**)&hl, s_h_lo);
    cudaGetSymbolAddress((void**)&sgh, s_sg_hi); cudaGetSymbolAddress((void**)&sgl, s_sg_lo);
    cudaGetSymbolAddress((void**)&r1h, s_r1_hi); cudaGetSymbolAddress((void**)&r1l, s_r1_lo);
    cudaGetSymbolAddress((void**)&r2h, s_r2_hi); cudaGetSymbolAddress((void**)&r2l, s_r2_lo);
    cudaGetSymbolAddress((void**)&Wxh, w_Wx_hi); cudaGetSymbolAddress((void**)&Wxl, w_Wx_lo);
    cudaGetSymbolAddress((void**)&Uxh, w_Ux_hi); cudaGetSymbolAddress((void**)&Uxl, w_Ux_lo);
    cudaGetSymbolAddress((void**)&a1h, w_a1_hi); cudaGetSymbolAddress((void**)&a1l, w_a1_lo);
    cudaGetSymbolAddress((void**)&swh, w_sw_hi); cudaGetSymbolAddress((void**)&swl, w_sw_lo);
    cudaGetSymbolAddress((void**)&w1h, w_r1_hi); cudaGetSymbolAddress((void**)&w1l, w_r1_lo);
    cudaGetSymbolAddress((void**)&w2h, w_r2_hi); cudaGetSymbolAddress((void**)&w2l, w_r2_lo);
    cudaGetSymbolAddress((void**)&w3h, w_r3_hi); cudaGetSymbolAddress((void**)&w3l, w_r3_lo);
    cudaGetSymbolAddress((void**)&gates, g_gates);
    cudaGetSymbolAddress((void**)&ah, g_ah);
    cudaGetSymbolAddress((void**)&alpha, g_alpha);

    cudaFuncSetAttribute(mega, cudaFuncAttributeMaxDynamicSharedMemorySize, SMEM_BYTES);

    const dim3 blk(256);

    // launch 1: all conversions + counter zeroing
    cvt_all<<<CVT_TOT, blk>>>((const float4*)x, (const float4*)h_prev, (const float4*)ssg_st,
                              (const float4*)Wx, (const float4*)Ux, (const float4*)a1_w,
                              (const float4*)ssg_w, (const float4*)r1_w,
                              (const float4*)r2_w, (const float4*)r3_w,
                              (uint4*)xh, (uint4*)xl, (uint4*)hh, (uint4*)hl,
                              (uint4*)sgh, (uint4*)sgl,
                              (uint4*)Wxh, (uint4*)Wxl, (uint4*)Uxh, (uint4*)Uxl,
                              (uint4*)a1h, (uint4*)a1l, (uint4*)swh, (uint4*)swl,
                              (uint4*)w1h, (uint4*)w1l, (uint4*)w2h, (uint4*)w2l,
                              (uint4*)w3h, (uint4*)w3l);

    // launch 2: mega dependency-graph GEMM schedule
    DescPack P = {};
    P.d[0] = { xh, xl, Wxh, Wxl, hh, hl, Uxh, Uxl, bWx, bUx,
               gates, nullptr, nullptr, 1024, 1024, 1024, 1024, 32, 32, NG, 2, NG/128 };
    P.d[1] = { xh, xl, a1h, a1l, hh, hl, a1h + 1024, a1l + 1024, a1_b, nullptr,
               ah, nullptr, nullptr, 1024, 2048, 1024, 2048, 32, 32, HH, 1, HH/128 };
    P.d[2] = { sgh, sgl, swh, swl, nullptr, nullptr, nullptr, nullptr, ssg_b, nullptr,
               out_ssg, nullptr, nullptr, 1024, 1024, 0, 0, 32, 0, HH, 0, HH/128 };
    P.d[3] = { hh, hl, w1h, w1l, nullptr, nullptr, nullptr, nullptr, r1_b, nullptr,
               nullptr, r1h, r1l, 1024, 1024, 0, 0, 32, 0, HH, 4, HH/128 };
    P.d[4] = { r1h, r1l, w2h, w2l, nullptr, nullptr, nullptr, nullptr, r2_b, nullptr,
               nullptr, r2h, r2l, 1024, 1024, 0, 0, 32, 0, HH, 4, HH/128 };
    P.d[5] = { r2h, r2l, w3h, w3l, nullptr, nullptr, nullptr, nullptr, r3_b, nullptr,
               nullptr, nullptr, nullptr, 1024, 1024, 0, 0, 32, 0, HH, 3, HH/128 };
    P.starts[0] = 0;    P.starts[1] = 1280; P.starts[2] = 1536; P.starts[3] = 1792;
    P.starts[4] = 2080; P.starts[5] = 2336; P.starts[6] = 2592;

    mega<<<MEGA_BLOCKS, blk, SMEM_BYTES>>>(P, gates, c_prev, alpha, out_ssg,
                                           out_h, out_c, ah, a2_w, a2_b);
}

// round 15
// speedup vs baseline: 1.2042x; 1.0019x over previous
#include <cuda_runtime.h>
#include <cuda_bf16.h>
#include <math.h>
#include <stdint.h>

#define BB 4096
#define HH 1024
#define NG 5120
#define BH (4096*1024)

// GEMM tiling: CTA 128x128, 8 warps (2x4), warp 64x32, K-step 32, 2-stage, 2 CTAs/SM
// single __syncthreads per stage (issue moved after the barrier covers the WAR)
#define RS 40                        // padded smem row stride (bf16) = 80B
#define ARR_BYTES (128*RS*2)         // 10240 per tile array
#define STG_BYTES (4*ARR_BYTES)      // 40960 per stage (Ah,Al,Wh,Wl)
#define SMEM_BYTES (2*STG_BYTES)     // 81920 double-buffered

// ---------------- scratch (device globals; no allocs) ----------------
__device__ __nv_bfloat16 s_x_hi[(size_t)BB*HH],  s_x_lo[(size_t)BB*HH];
__device__ __nv_bfloat16 s_h_hi[(size_t)BB*HH],  s_h_lo[(size_t)BB*HH];
__device__ __nv_bfloat16 s_sg_hi[(size_t)BB*HH], s_sg_lo[(size_t)BB*HH];
__device__ __nv_bfloat16 s_r1_hi[(size_t)BB*HH], s_r1_lo[(size_t)BB*HH];
__device__ __nv_bfloat16 s_r2_hi[(size_t)BB*HH], s_r2_lo[(size_t)BB*HH];
__device__ __nv_bfloat16 w_Wx_hi[(size_t)NG*HH], w_Wx_lo[(size_t)NG*HH];
__device__ __nv_bfloat16 w_Ux_hi[(size_t)NG*HH], w_Ux_lo[(size_t)NG*HH];
__device__ __nv_bfloat16 w_a1_hi[(size_t)HH*2048], w_a1_lo[(size_t)HH*2048];
__device__ __nv_bfloat16 w_sw_hi[(size_t)HH*HH], w_sw_lo[(size_t)HH*HH];
__device__ __nv_bfloat16 w_r1_hi[(size_t)HH*HH], w_r1_lo[(size_t)HH*HH];
__device__ __nv_bfloat16 w_r2_hi[(size_t)HH*HH], w_r2_lo[(size_t)HH*HH];
__device__ __nv_bfloat16 w_r3_hi[(size_t)HH*HH], w_r3_lo[(size_t)HH*HH];
__device__ float g_gates[(size_t)BB*NG];
__device__ float g_ah[(size_t)BB*HH];
__device__ float g_alpha[BB];
// sync counters: [0..32) gates_rb  [32..64) ah_rb  [64..96) ssg_rb
//                [96..128) r1_rb   [128..160) alpha_ch  [160..192) r2_rb
__device__ int g_cnt[256];

// ---------------- helpers ----------------
__device__ __forceinline__ uint32_t smem_u32(const void* p) {
    uint32_t a;
    asm("{ .reg .u64 t; cvta.to.shared.u64 t, %1; cvt.u32.u64 %0, t; }" : "=r"(a) : "l"(p));
    return a;
}
__device__ __forceinline__ void ldsm4(uint32_t& r0, uint32_t& r1, uint32_t& r2, uint32_t& r3, uint32_t a) {
    asm volatile("ldmatrix.sync.aligned.m8n8.x4.shared.b16 {%0,%1,%2,%3}, [%4];"
        : "=r"(r0), "=r"(r1), "=r"(r2), "=r"(r3) : "r"(a));
}
__device__ __forceinline__ void mma16816(float* c, const uint32_t* a, const uint32_t* b) {
    asm volatile("mma.sync.aligned.m16n8k16.row.col.f32.bf16.bf16.f32 "
        "{%0,%1,%2,%3}, {%4,%5,%6,%7}, {%8,%9}, {%0,%1,%2,%3};"
        : "+f"(c[0]), "+f"(c[1]), "+f"(c[2]), "+f"(c[3])
        : "r"(a[0]), "r"(a[1]), "r"(a[2]), "r"(a[3]), "r"(b[0]), "r"(b[1]));
}
#define CP_ASYNC16(dst, src) \
    asm volatile("cp.async.cg.shared.global [%0], [%1], 16;" :: "r"(dst), "l"(src))
#define CP_COMMIT()  asm volatile("cp.async.commit_group;" ::: "memory")
#define CP_WAIT(n)   asm volatile("cp.async.wait_group %0;" :: "n"(n) : "memory")

__device__ __forceinline__ int ld_acq(const int* p) {
    int v; asm volatile("ld.acquire.gpu.global.s32 %0, [%1];" : "=r"(v) : "l"(p) : "memory");
    return v;
}
__device__ __forceinline__ void spin_wait(const int* c, int target) {
    if (threadIdx.x == 0) {
        while (ld_acq(c) < target) __nanosleep(128);
    }
    __syncthreads();
}
__device__ __forceinline__ void signal_cnt(int* c) {
    __threadfence();
    __syncthreads();
    if (threadIdx.x == 0) atomicAdd(c, 1);
}

__device__ __forceinline__ float tanh_fast(float v) {
    return 2.f / (1.f + __expf(-2.f * v)) - 1.f;
}

__device__ __forceinline__ void split2(float v0, float v1, __nv_bfloat162& hi, __nv_bfloat162& lo) {
    __nv_bfloat16 h0 = __float2bfloat16_rn(v0), h1 = __float2bfloat16_rn(v1);
    __nv_bfloat16 l0 = __float2bfloat16_rn(v0 - __bfloat162float(h0));
    __nv_bfloat16 l1 = __float2bfloat16_rn(v1 - __bfloat162float(h1));
    hi = __nv_bfloat162(h0, h1); lo = __nv_bfloat162(l0, l1);
}
__device__ __forceinline__ uint32_t b2u(__nv_bfloat162 v) {
    uint32_t u; *(__nv_bfloat162*)&u = v; return u;
}
// 8 floats -> 16B hi + 16B lo, paired bf16x2 conversions
__device__ __forceinline__ void split8(float4 a, float4 b, uint4& hi, uint4& lo) {
    float2 a01 = make_float2(a.x, a.y), a23 = make_float2(a.z, a.w);
    float2 b01 = make_float2(b.x, b.y), b23 = make_float2(b.z, b.w);
    __nv_bfloat162 h0 = __float22bfloat162_rn(a01);
    __nv_bfloat162 h1 = __float22bfloat162_rn(a23);
    __nv_bfloat162 h2 = __float22bfloat162_rn(b01);
    __nv_bfloat162 h3 = __float22bfloat162_rn(b23);
    float2 f0 = __bfloat1622float2(h0), f1 = __bfloat1622float2(h1);
    float2 f2 = __bfloat1622float2(h2), f3 = __bfloat1622float2(h3);
    __nv_bfloat162 l0 = __float22bfloat162_rn(make_float2(a01.x - f0.x, a01.y - f0.y));
    __nv_bfloat162 l1 = __float22bfloat162_rn(make_float2(a23.x - f1.x, a23.y - f1.y));
    __nv_bfloat162 l2 = __float22bfloat162_rn(make_float2(b01.x - f2.x, b01.y - f2.y));
    __nv_bfloat162 l3 = __float22bfloat162_rn(make_float2(b23.x - f3.x, b23.y - f3.y));
    hi.x = b2u(h0); hi.y = b2u(h1); hi.z = b2u(h2); hi.w = b2u(h3);
    lo.x = b2u(l0); lo.y = b2u(l1); lo.z = b2u(l2); lo.w = b2u(l3);
}

// ---------------- single conversion kernel (act + weights + counter zero) ----------------
#define CVT_ACT_B 2048          // BH/8/256
#define GW1 655360              // Wx groups (5120*1024/8)
#define GW2 1310720             // +Ux
#define GW3 1572864             // +a1
#define GWS 131072              // each H*H/8
#define CVT_TOT 10240           // 2048 + 8192

__global__ void __launch_bounds__(256)
cvt_all(const float4* __restrict__ x, const float4* __restrict__ h, const float4* __restrict__ ssg,
        const float4* __restrict__ Wx, const float4* __restrict__ Ux, const float4* __restrict__ a1,
        const float4* __restrict__ sw, const float4* __restrict__ r1,
        const float4* __restrict__ r2, const float4* __restrict__ r3,
        uint4* __restrict__ xh, uint4* __restrict__ xl,
        uint4* __restrict__ hh, uint4* __restrict__ hl,
        uint4* __restrict__ sgh, uint4* __restrict__ sgl,
        uint4* __restrict__ Wxh, uint4* __restrict__ Wxl,
        uint4* __restrict__ Uxh, uint4* __restrict__ Uxl,
        uint4* __restrict__ a1h, uint4* __restrict__ a1l,
        uint4* __restrict__ swh, uint4* __restrict__ swl,
        uint4* __restrict__ w1h, uint4* __restrict__ w1l,
        uint4* __restrict__ w2h, uint4* __restrict__ w2l,
        uint4* __restrict__ w3h, uint4* __restrict__ w3l)
{
    if (blockIdx.x == 0) g_cnt[threadIdx.x] = 0;      // zero counters each replay
    const int b = blockIdx.x;
    if (b < CVT_ACT_B) {
        int i = b * 256 + threadIdx.x;                // BH/8 groups
        float4 x0 = x[2*i], x1 = x[2*i+1];
        float4 h0 = h[2*i], h1 = h[2*i+1];
        float4 s0 = ssg[2*i], s1 = ssg[2*i+1];
        uint4 hi, lo;
        split8(x0, x1, hi, lo); xh[i] = hi; xl[i] = lo;
        split8(h0, h1, hi, lo); hh[i] = hi; hl[i] = lo;
        s0.x += h0.x; s0.y += h0.y; s0.z += h0.z; s0.w += h0.w;
        s1.x += h1.x; s1.y += h1.y; s1.z += h1.z; s1.w += h1.w;
        split8(s0, s1, hi, lo); sgh[i] = hi; sgl[i] = lo;
    } else {
        int i = (b - CVT_ACT_B) * 256 + threadIdx.x;
        const float4* src; uint4 *oh, *ol; int j;
        if      (i < GW1)          { src = Wx; oh = Wxh; ol = Wxl; j = i; }
        else if (i < GW2)          { src = Ux; oh = Uxh; ol = Uxl; j = i - GW1; }
        else if (i < GW3)          { src = a1; oh = a1h; ol = a1l; j = i - GW2; }
        else if (i < GW3 + GWS)    { src = sw; oh = swh; ol = swl; j = i - GW3; }
        else if (i < GW3 + 2*GWS)  { src = r1; oh = w1h; ol = w1l; j = i - GW3 - GWS; }
        else if (i < GW3 + 3*GWS)  { src = r2; oh = w2h; ol = w2l; j = i - GW3 - 2*GWS; }
        else                       { src = r3; oh = w3h; ol = w3l; j = i - GW3 - 3*GWS; }
        float4 v0 = src[2*j], v1 = src[2*j+1];
        uint4 hi, lo;
        split8(v0, v1, hi, lo);
        oh[j] = hi; ol[j] = lo;
    }
}

// ---------------- multi-GEMM descriptor ----------------
// modes: 0 fp32 out ; 1 relu fp32 ; 2 gate acts ; 3 r3+cell fused ; 4 relu + bf16 pair out
struct GemmDesc {
    const __nv_bfloat16 *A1h, *A1l, *W1h, *W1l;
    const __nv_bfloat16 *A2h, *A2l, *W2h, *W2l;
    const float *b1, *b2;
    float* Cf; __nv_bfloat16* Chi; __nv_bfloat16* Clo;
    int lda1, ldw1, lda2, ldw2;
    int s1, s2;          // number of K=32 chunks per operand pair
    int ldc, mode, nx;
};
struct DescPack {
    GemmDesc d[6];
    int starts[7];
};

// mega grid layout
#define ALPHA_B0 2048
#define ALPHA_B1 2080
#define MEGA_BLOCKS 2592

// ---------------- persistent dependency-graph mega GEMM kernel ----------------
__global__ void __launch_bounds__(256, 2)
mega(const __grid_constant__ DescPack P,
     const float* __restrict__ gates, const float* __restrict__ c_prev,
     float* __restrict__ alphav, const float* __restrict__ ssg,
     float* __restrict__ out_h, float* __restrict__ out_c,
     const float* __restrict__ ahbuf, const float* __restrict__ a2w,
     const float* __restrict__ a2b)
{
    extern __shared__ char smem[];
    const int tid = threadIdx.x;
    const int bid = blockIdx.x;

    // ---- alpha reduction blocks ----
    if (bid >= ALPHA_B0 && bid < ALPHA_B1) {
        const int mc = bid - ALPHA_B0;
        spin_wait(&g_cnt[32 + mc], 8);                // ah row-block complete
        const int l8 = tid & 7, r0 = tid >> 3;
#pragma unroll
        for (int p = 0; p < 4; ++p) {
            const int m = mc * 128 + p * 32 + r0;
            float s = 0.f;
            for (int k = l8; k < 1024; k += 8)
                s += ahbuf[(size_t)m * 1024 + k] * a2w[k];
            s += __shfl_down_sync(0xffffffffu, s, 4);
            s += __shfl_down_sync(0xffffffffu, s, 2);
            s += __shfl_down_sync(0xffffffffu, s, 1);
            if (l8 == 0) alphav[m] = 1.f / (1.f + __expf(-(s + a2b[0])));
        }
        signal_cnt(&g_cnt[128 + mc]);
        return;
    }

    const uint32_t sbase = smem_u32(smem);
    const int wid = tid >> 5, lane = tid & 31;
    const int wm = wid >> 2, wn = wid & 3;

    int t = bid, di = 0;
    while (di + 1 < 6 && t >= P.starts[di + 1]) ++di;
    const GemmDesc& d = P.d[di];
    const int rel = t - P.starts[di];
    const int m0 = (rel / d.nx) * 128, n0 = (rel % d.nx) * 128;
    const int rb = m0 >> 7;
    const int s1 = d.s1, S = d.s1 + d.s2;

    // mainloop input dependencies
    if (di == 4) spin_wait(&g_cnt[96 + rb], 8);       // r2 waits r1 row-block
    if (di == 5) spin_wait(&g_cnt[160 + rb], 8);      // r3 waits r2 row-block

    float acc[4][4][4];
#pragma unroll
    for (int a = 0; a < 4; ++a)
#pragma unroll
        for (int b = 0; b < 4; ++b)
#pragma unroll
            for (int q = 0; q < 4; ++q) acc[a][b][q] = 0.f;

    auto issue_load = [&](int s) {
        const __nv_bfloat16 *Ah, *Al, *Wh, *Wl; int lda, ldw, koff;
        if (s < s1) { Ah = d.A1h; Al = d.A1l; Wh = d.W1h; Wl = d.W1l; lda = d.lda1; ldw = d.ldw1; koff = s * 32; }
        else        { Ah = d.A2h; Al = d.A2l; Wh = d.W2h; Wl = d.W2l; lda = d.lda2; ldw = d.ldw2; koff = (s - s1) * 32; }
        const __nv_bfloat16* srcs[4] = {Ah, Al, Wh, Wl};
        uint32_t dst0 = sbase + (uint32_t)(s & 1) * STG_BYTES;
#pragma unroll
        for (int arr = 0; arr < 4; ++arr) {
            const __nv_bfloat16* src = srcs[arr];
            int ldx = (arr < 2) ? lda : ldw;
#pragma unroll
            for (int i = 0; i < 2; ++i) {
                int idx = tid + i * 256;
                int row = idx >> 2, c = idx & 3;
                int rbase = (arr < 2) ? m0 : n0;
                const __nv_bfloat16* g = src + (size_t)(rbase + row) * ldx + koff + c * 8;
                uint32_t dsta = dst0 + arr * ARR_BYTES + row * 80 + c * 16;
                CP_ASYNC16(dsta, g);
            }
        }
        CP_COMMIT();
    };

    issue_load(0);

    for (int s = 0; s < S; ++s) {
        CP_WAIT(0);              // only group s is in flight here; wait for it
        __syncthreads();         // all warps done compute(s-1) -> buf (s+1)&1 free; stage-s data visible
        if (s + 1 < S) issue_load(s + 1);

        uint32_t SB = sbase + (uint32_t)(s & 1) * STG_BYTES;
        uint32_t Ahb = SB, Alb = SB + ARR_BYTES;
        uint32_t Whb = SB + 2 * ARR_BYTES, Wlb = SB + 3 * ARR_BYTES;

#pragma unroll
        for (int k16 = 0; k16 < 2; ++k16) {
            const int k0 = k16 * 16;
            uint32_t bh[4][2], bl[4][2];
            {
                const int g = lane >> 3;
                const int rbw = wn * 32 + ((g >> 1) << 3) + (lane & 7);
                const int cb = k0 + ((g & 1) << 3);
#pragma unroll
                for (int p = 0; p < 2; ++p) {
                    uint32_t off = (uint32_t)((rbw + p * 16) * RS + cb) * 2;
                    ldsm4(bh[2*p][0], bh[2*p][1], bh[2*p+1][0], bh[2*p+1][1], Whb + off);
                    ldsm4(bl[2*p][0], bl[2*p][1], bl[2*p+1][0], bl[2*p+1][1], Wlb + off);
                }
            }
            const int ra = wm * 64 + (lane & 15);
            const int ca = k0 + ((lane >> 4) << 3);
            uint32_t ah[2][4], al[2][4];
            {
                uint32_t off0 = (uint32_t)(ra * RS + ca) * 2;
                ldsm4(ah[0][0], ah[0][1], ah[0][2], ah[0][3], Ahb + off0);
                ldsm4(al[0][0], al[0][1], al[0][2], al[0][3], Alb + off0);
            }
#pragma unroll
            for (int mb = 0; mb < 4; ++mb) {
                const int cur = mb & 1, nxt = cur ^ 1;
                if (mb < 3) {
                    uint32_t off = (uint32_t)((ra + (mb + 1) * 16) * RS + ca) * 2;
                    ldsm4(ah[nxt][0], ah[nxt][1], ah[nxt][2], ah[nxt][3], Ahb + off);
                    ldsm4(al[nxt][0], al[nxt][1], al[nxt][2], al[nxt][3], Alb + off);
                }
#pragma unroll
                for (int nb = 0; nb < 4; ++nb) mma16816(acc[mb][nb], ah[cur], bh[nb]);
#pragma unroll
                for (int nb = 0; nb < 4; ++nb) mma16816(acc[mb][nb], ah[cur], bl[nb]);
#pragma unroll
                for (int nb = 0; nb < 4; ++nb) mma16816(acc[mb][nb], al[cur], bh[nb]);
            }
        }
        // no bottom barrier: next iteration's top barrier covers the WAR on buf s&1
    }

    // r3 epilogue dependencies (deferred past mainloop for overlap)
    if (di == 5) {
        spin_wait(&g_cnt[0 + rb], 40);    // gates row-block
        spin_wait(&g_cnt[64 + rb], 8);    // ssg row-block
        spin_wait(&g_cnt[128 + rb], 1);   // alpha chunk
    }

    // ---------------- epilogue ----------------
    const int mode = d.mode;
#pragma unroll
    for (int mb = 0; mb < 4; ++mb) {
#pragma unroll
        for (int nb = 0; nb < 4; ++nb) {
#pragma unroll
            for (int h = 0; h < 2; ++h) {
                const int m = m0 + wm * 64 + mb * 16 + (lane >> 2) + h * 8;
                const int n = n0 + wn * 32 + nb * 8 + 2 * (lane & 3);
                float v0 = acc[mb][nb][2 * h]     + d.b1[n];
                float v1 = acc[mb][nb][2 * h + 1] + d.b1[n + 1];
                if (d.b2) { v0 += d.b2[n]; v1 += d.b2[n + 1]; }
                if (mode == 1 || mode == 4) { v0 = fmaxf(v0, 0.f); v1 = fmaxf(v1, 0.f); }
                if (mode == 2) {
                    const int g = n >> 10;
                    if (g == 3) { v0 = tanh_fast(v0); v1 = tanh_fast(v1); }
                    else { v0 = 1.f / (1.f + __expf(-v0)); v1 = 1.f / (1.f + __expf(-v1)); }
                }
                const size_t gm = (size_t)m * d.ldc + n;
                if (mode == 4) {
                    __nv_bfloat162 hi2, lo2;
                    split2(v0, v1, hi2, lo2);
                    *(__nv_bfloat162*)(d.Chi + gm) = hi2;
                    *(__nv_bfloat162*)(d.Clo + gm) = lo2;
                } else if (mode == 3) {
                    const size_t gb = (size_t)m * NG + n;
                    const float a = alphav[m];
                    float2 cp = *(const float2*)(c_prev + gm);
                    float2 sg = *(const float2*)(ssg + gm);
                    float c0 = gates[gb + 1024] * cp.x
                             + gates[gb] * gates[gb + 3072] * gates[gb + 4096] * a * sg.x + v0;
                    float c1 = gates[gb + 1025] * cp.y
                             + gates[gb + 1] * gates[gb + 3073] * gates[gb + 4097] * a * sg.y + v1;
                    float2 oc; oc.x = c0; oc.y = c1;
                    float2 oh; oh.x = gates[gb + 2048] * tanh_fast(c0);
                    oh.y = gates[gb + 2049] * tanh_fast(c1);
                    *(float2*)(out_c + gm) = oc;
                    *(float2*)(out_h + gm) = oh;
                } else {
                    float2 o; o.x = v0; o.y = v1;
                    *(float2*)(d.Cf + gm) = o;
                }
            }
        }
    }

    // completion signals
    if      (di == 0) signal_cnt(&g_cnt[0 + rb]);
    else if (di == 1) signal_cnt(&g_cnt[32 + rb]);
    else if (di == 2) signal_cnt(&g_cnt[64 + rb]);
    else if (di == 3) signal_cnt(&g_cnt[96 + rb]);
    else if (di == 4) signal_cnt(&g_cnt[160 + rb]);
}

// ---------------- launch ----------------
extern "C" void kernel_launch(void* const* d_in, const int* in_sizes, int n_in,
                              void* d_out, int out_size)
{
    const float* x      = (const float*)d_in[0];
    const float* h_prev = (const float*)d_in[1];
    const float* c_prev = (const float*)d_in[2];
    const float* ssg_st = (const float*)d_in[3];
    const float* Wx     = (const float*)d_in[4];
    const float* bWx    = (const float*)d_in[5];
    const float* Ux     = (const float*)d_in[6];
    const float* bUx    = (const float*)d_in[7];
    const float* a1_w   = (const float*)d_in[8];
    const float* a1_b   = (const float*)d_in[9];
    const float* a2_w   = (const float*)d_in[10];
    const float* a2_b   = (const float*)d_in[11];
    const float* r1_w   = (const float*)d_in[12];
    const float* r1_b   = (const float*)d_in[13];
    const float* r2_w   = (const float*)d_in[14];
    const float* r2_b   = (const float*)d_in[15];
    const float* r3_w   = (const float*)d_in[16];
    const float* r3_b   = (const float*)d_in[17];
    const float* ssg_w  = (const float*)d_in[18];
    const float* ssg_b  = (const float*)d_in[19];

    float* out = (float*)d_out;
    float* out_h   = out;
    float* out_c   = out + (size_t)BH;
    float* out_ssg = out + 2 * (size_t)BH;

    __nv_bfloat16 *xh, *xl, *hh, *hl, *sgh, *sgl, *r1h, *r1l, *r2h, *r2l;
    __nv_bfloat16 *Wxh, *Wxl, *Uxh, *Uxl, *a1h, *a1l, *swh, *swl, *w1h, *w1l, *w2h, *w2l, *w3h, *w3l;
    float *gates, *ah, *alpha;
    cudaGetSymbolAddress((void**)&xh, s_x_hi);   cudaGetSymbolAddress((void**)&xl, s_x_lo);
    cudaGetSymbolAddress((void**)&hh, s_h_hi);   cudaGetSymbolAddress((void**)&hl, s_h_lo);
    cudaGetSymbolAddress((void**)&sgh, s_sg_hi); cudaGetSymbolAddress((void**)&sgl, s_sg_lo);
    cudaGetSymbolAddress((void**)&r1h, s_r1_hi); cudaGetSymbolAddress((void**)&r1l, s_r1_lo);
    cudaGetSymbolAddress((void**)&r2h, s_r2_hi); cudaGetSymbolAddress((void**)&r2l, s_r2_lo);
    cudaGetSymbolAddress((void**)&Wxh, w_Wx_hi); cudaGetSymbolAddress((void**)&Wxl, w_Wx_lo);
    cudaGetSymbolAddress((void**)&Uxh, w_Ux_hi); cudaGetSymbolAddress((void**)&Uxl, w_Ux_lo);
    cudaGetSymbolAddress((void**)&a1h, w_a1_hi); cudaGetSymbolAddress((void**)&a1l, w_a1_lo);
    cudaGetSymbolAddress((void**)&swh, w_sw_hi); cudaGetSymbolAddress((void**)&swl, w_sw_lo);
    cudaGetSymbolAddress((void**)&w1h, w_r1_hi); cudaGetSymbolAddress((void**)&w1l, w_r1_lo);
    cudaGetSymbolAddress((void**)&w2h, w_r2_hi); cudaGetSymbolAddress((void**)&w2l, w_r2_lo);
    cudaGetSymbolAddress((void**)&w3h, w_r3_hi); cudaGetSymbolAddress((void**)&w3l, w_r3_lo);
    cudaGetSymbolAddress((void**)&gates, g_gates);
    cudaGetSymbolAddress((void**)&ah, g_ah);
    cudaGetSymbolAddress((void**)&alpha, g_alpha);

    cudaFuncSetAttribute(mega, cudaFuncAttributeMaxDynamicSharedMemorySize, SMEM_BYTES);

    const dim3 blk(256);

    // launch 1: all conversions + counter zeroing
    cvt_all<<<CVT_TOT, blk>>>((const float4*)x, (const float4*)h_prev, (const float4*)ssg_st,
                              (const float4*)Wx, (const float4*)Ux, (const float4*)a1_w,
                              (const float4*)ssg_w, (const float4*)r1_w,
                              (const float4*)r2_w, (const float4*)r3_w,
                              (uint4*)xh, (uint4*)xl, (uint4*)hh, (uint4*)hl,
                              (uint4*)sgh, (uint4*)sgl,
                              (uint4*)Wxh, (uint4*)Wxl, (uint4*)Uxh, (uint4*)Uxl,
                              (uint4*)a1h, (uint4*)a1l, (uint4*)swh, (uint4*)swl,
                              (uint4*)w1h, (uint4*)w1l, (uint4*)w2h, (uint4*)w2l,
                              (uint4*)w3h, (uint4*)w3l);

    // launch 2: mega dependency-graph GEMM schedule
    DescPack P = {};
    P.d[0] = { xh, xl, Wxh, Wxl, hh, hl, Uxh, Uxl, bWx, bUx,
               gates, nullptr, nullptr, 1024, 1024, 1024, 1024, 32, 32, NG, 2, NG/128 };
    P.d[1] = { xh, xl, a1h, a1l, hh, hl, a1h + 1024, a1l + 1024, a1_b, nullptr,
               ah, nullptr, nullptr, 1024, 2048, 1024, 2048, 32, 32, HH, 1, HH/128 };
    P.d[2] = { sgh, sgl, swh, swl, nullptr, nullptr, nullptr, nullptr, ssg_b, nullptr,
               out_ssg, nullptr, nullptr, 1024, 1024, 0, 0, 32, 0, HH, 0, HH/128 };
    P.d[3] = { hh, hl, w1h, w1l, nullptr, nullptr, nullptr, nullptr, r1_b, nullptr,
               nullptr, r1h, r1l, 1024, 1024, 0, 0, 32, 0, HH, 4, HH/128 };
    P.d[4] = { r1h, r1l, w2h, w2l, nullptr, nullptr, nullptr, nullptr, r2_b, nullptr,
               nullptr, r2h, r2l, 1024, 1024, 0, 0, 32, 0, HH, 4, HH/128 };
    P.d[5] = { r2h, r2l, w3h, w3l, nullptr, nullptr, nullptr, nullptr, r3_b, nullptr,
               nullptr, nullptr, nullptr, 1024, 1024, 0, 0, 32, 0, HH, 3, HH/128 };
    P.starts[0] = 0;    P.starts[1] = 1280; P.starts[2] = 1536; P.starts[3] = 1792;
    P.starts[4] = 2080; P.starts[5] = 2336; P.starts[6] = 2592;

    mega<<<MEGA_BLOCKS, blk, SMEM_BYTES>>>(P, gates, c_prev, alpha, out_ssg,
                                           out_h, out_c, ah, a2_w, a2_b);
}

// round 16
// speedup vs baseline: 1.2317x; 1.0228x over previous
#include <cuda_runtime.h>
#include <cuda_bf16.h>
#include <math.h>
#include <stdint.h>

#define BB 4096
#define HH 1024
#define NG 5120
#define BH (4096*1024)

// GEMM tiling: CTA 128x128, 8 warps (2x4), warp 64x32, K-step 32, 2-stage, 2 CTAs/SM
// single __syncthreads per stage; cp.async issue hidden in the ldsm shadow
#define RS 40                        // padded smem row stride (bf16) = 80B
#define ARR_BYTES (128*RS*2)         // 10240 per tile array
#define STG_BYTES (4*ARR_BYTES)      // 40960 per stage (Ah,Al,Wh,Wl)
#define SMEM_BYTES (2*STG_BYTES)     // 81920 double-buffered

// ---------------- scratch (device globals; no allocs) ----------------
__device__ __nv_bfloat16 s_x_hi[(size_t)BB*HH],  s_x_lo[(size_t)BB*HH];
__device__ __nv_bfloat16 s_h_hi[(size_t)BB*HH],  s_h_lo[(size_t)BB*HH];
__device__ __nv_bfloat16 s_sg_hi[(size_t)BB*HH], s_sg_lo[(size_t)BB*HH];
__device__ __nv_bfloat16 s_r1_hi[(size_t)BB*HH], s_r1_lo[(size_t)BB*HH];
__device__ __nv_bfloat16 s_r2_hi[(size_t)BB*HH], s_r2_lo[(size_t)BB*HH];
__device__ __nv_bfloat16 w_Wx_hi[(size_t)NG*HH], w_Wx_lo[(size_t)NG*HH];
__device__ __nv_bfloat16 w_Ux_hi[(size_t)NG*HH], w_Ux_lo[(size_t)NG*HH];
__device__ __nv_bfloat16 w_a1_hi[(size_t)HH*2048], w_a1_lo[(size_t)HH*2048];
__device__ __nv_bfloat16 w_sw_hi[(size_t)HH*HH], w_sw_lo[(size_t)HH*HH];
__device__ __nv_bfloat16 w_r1_hi[(size_t)HH*HH], w_r1_lo[(size_t)HH*HH];
__device__ __nv_bfloat16 w_r2_hi[(size_t)HH*HH], w_r2_lo[(size_t)HH*HH];
__device__ __nv_bfloat16 w_r3_hi[(size_t)HH*HH], w_r3_lo[(size_t)HH*HH];
__device__ float g_gates[(size_t)BB*NG];
__device__ float g_ah[(size_t)BB*HH];
__device__ float g_alpha[BB];
// sync counters: [0..32) gates_rb  [32..64) ah_rb  [64..96) ssg_rb
//                [96..128) r1_rb   [128..160) alpha_ch  [160..192) r2_rb
__device__ int g_cnt[256];

// ---------------- helpers ----------------
__device__ __forceinline__ uint32_t smem_u32(const void* p) {
    uint32_t a;
    asm("{ .reg .u64 t; cvta.to.shared.u64 t, %1; cvt.u32.u64 %0, t; }" : "=r"(a) : "l"(p));
    return a;
}
__device__ __forceinline__ void ldsm4(uint32_t& r0, uint32_t& r1, uint32_t& r2, uint32_t& r3, uint32_t a) {
    asm volatile("ldmatrix.sync.aligned.m8n8.x4.shared.b16 {%0,%1,%2,%3}, [%4];"
        : "=r"(r0), "=r"(r1), "=r"(r2), "=r"(r3) : "r"(a));
}
__device__ __forceinline__ void mma16816(float* c, const uint32_t* a, const uint32_t* b) {
    asm volatile("mma.sync.aligned.m16n8k16.row.col.f32.bf16.bf16.f32 "
        "{%0,%1,%2,%3}, {%4,%5,%6,%7}, {%8,%9}, {%0,%1,%2,%3};"
        : "+f"(c[0]), "+f"(c[1]), "+f"(c[2]), "+f"(c[3])
        : "r"(a[0]), "r"(a[1]), "r"(a[2]), "r"(a[3]), "r"(b[0]), "r"(b[1]));
}
#define CP_ASYNC16(dst, src) \
    asm volatile("cp.async.cg.shared.global [%0], [%1], 16;" :: "r"(dst), "l"(src))
#define CP_COMMIT()  asm volatile("cp.async.commit_group;" ::: "memory")
#define CP_WAIT(n)   asm volatile("cp.async.wait_group %0;" :: "n"(n) : "memory")

__device__ __forceinline__ int ld_acq(const int* p) {
    int v; asm volatile("ld.acquire.gpu.global.s32 %0, [%1];" : "=r"(v) : "l"(p) : "memory");
    return v;
}
__device__ __forceinline__ void spin_wait(const int* c, int target) {
    if (threadIdx.x == 0) {
        while (ld_acq(c) < target) __nanosleep(128);
    }
    __syncthreads();
}
__device__ __forceinline__ void signal_cnt(int* c) {
    __threadfence();
    __syncthreads();
    if (threadIdx.x == 0) atomicAdd(c, 1);
}

__device__ __forceinline__ float tanh_fast(float v) {
    return 2.f / (1.f + __expf(-2.f * v)) - 1.f;
}

__device__ __forceinline__ void split2(float v0, float v1, __nv_bfloat162& hi, __nv_bfloat162& lo) {
    __nv_bfloat16 h0 = __float2bfloat16_rn(v0), h1 = __float2bfloat16_rn(v1);
    __nv_bfloat16 l0 = __float2bfloat16_rn(v0 - __bfloat162float(h0));
    __nv_bfloat16 l1 = __float2bfloat16_rn(v1 - __bfloat162float(h1));
    hi = __nv_bfloat162(h0, h1); lo = __nv_bfloat162(l0, l1);
}
__device__ __forceinline__ uint32_t b2u(__nv_bfloat162 v) {
    uint32_t u; *(__nv_bfloat162*)&u = v; return u;
}
// 8 floats -> 16B hi + 16B lo, paired bf16x2 conversions
__device__ __forceinline__ void split8(float4 a, float4 b, uint4& hi, uint4& lo) {
    float2 a01 = make_float2(a.x, a.y), a23 = make_float2(a.z, a.w);
    float2 b01 = make_float2(b.x, b.y), b23 = make_float2(b.z, b.w);
    __nv_bfloat162 h0 = __float22bfloat162_rn(a01);
    __nv_bfloat162 h1 = __float22bfloat162_rn(a23);
    __nv_bfloat162 h2 = __float22bfloat162_rn(b01);
    __nv_bfloat162 h3 = __float22bfloat162_rn(b23);
    float2 f0 = __bfloat1622float2(h0), f1 = __bfloat1622float2(h1);
    float2 f2 = __bfloat1622float2(h2), f3 = __bfloat1622float2(h3);
    __nv_bfloat162 l0 = __float22bfloat162_rn(make_float2(a01.x - f0.x, a01.y - f0.y));
    __nv_bfloat162 l1 = __float22bfloat162_rn(make_float2(a23.x - f1.x, a23.y - f1.y));
    __nv_bfloat162 l2 = __float22bfloat162_rn(make_float2(b01.x - f2.x, b01.y - f2.y));
    __nv_bfloat162 l3 = __float22bfloat162_rn(make_float2(b23.x - f3.x, b23.y - f3.y));
    hi.x = b2u(h0); hi.y = b2u(h1); hi.z = b2u(h2); hi.w = b2u(h3);
    lo.x = b2u(l0); lo.y = b2u(l1); lo.z = b2u(l2); lo.w = b2u(l3);
}

// ---------------- single conversion kernel (act + weights + counter zero) ----------------
#define CVT_ACT_B 2048          // BH/8/256
#define GW1 655360              // Wx groups (5120*1024/8)
#define GW2 1310720             // +Ux
#define GW3 1572864             // +a1
#define GWS 131072              // each H*H/8
#define CVT_TOT 10240           // 2048 + 8192

__global__ void __launch_bounds__(256)
cvt_all(const float4* __restrict__ x, const float4* __restrict__ h, const float4* __restrict__ ssg,
        const float4* __restrict__ Wx, const float4* __restrict__ Ux, const float4* __restrict__ a1,
        const float4* __restrict__ sw, const float4* __restrict__ r1,
        const float4* __restrict__ r2, const float4* __restrict__ r3,
        uint4* __restrict__ xh, uint4* __restrict__ xl,
        uint4* __restrict__ hh, uint4* __restrict__ hl,
        uint4* __restrict__ sgh, uint4* __restrict__ sgl,
        uint4* __restrict__ Wxh, uint4* __restrict__ Wxl,
        uint4* __restrict__ Uxh, uint4* __restrict__ Uxl,
        uint4* __restrict__ a1h, uint4* __restrict__ a1l,
        uint4* __restrict__ swh, uint4* __restrict__ swl,
        uint4* __restrict__ w1h, uint4* __restrict__ w1l,
        uint4* __restrict__ w2h, uint4* __restrict__ w2l,
        uint4* __restrict__ w3h, uint4* __restrict__ w3l)
{
    if (blockIdx.x == 0) g_cnt[threadIdx.x] = 0;      // zero counters each replay
    const int b = blockIdx.x;
    if (b < CVT_ACT_B) {
        int i = b * 256 + threadIdx.x;                // BH/8 groups
        float4 x0 = x[2*i], x1 = x[2*i+1];
        float4 h0 = h[2*i], h1 = h[2*i+1];
        float4 s0 = ssg[2*i], s1 = ssg[2*i+1];
        uint4 hi, lo;
        split8(x0, x1, hi, lo); xh[i] = hi; xl[i] = lo;
        split8(h0, h1, hi, lo); hh[i] = hi; hl[i] = lo;
        s0.x += h0.x; s0.y += h0.y; s0.z += h0.z; s0.w += h0.w;
        s1.x += h1.x; s1.y += h1.y; s1.z += h1.z; s1.w += h1.w;
        split8(s0, s1, hi, lo); sgh[i] = hi; sgl[i] = lo;
    } else {
        int i = (b - CVT_ACT_B) * 256 + threadIdx.x;
        const float4* src; uint4 *oh, *ol; int j;
        if      (i < GW1)          { src = Wx; oh = Wxh; ol = Wxl; j = i; }
        else if (i < GW2)          { src = Ux; oh = Uxh; ol = Uxl; j = i - GW1; }
        else if (i < GW3)          { src = a1; oh = a1h; ol = a1l; j = i - GW2; }
        else if (i < GW3 + GWS)    { src = sw; oh = swh; ol = swl; j = i - GW3; }
        else if (i < GW3 + 2*GWS)  { src = r1; oh = w1h; ol = w1l; j = i - GW3 - GWS; }
        else if (i < GW3 + 3*GWS)  { src = r2; oh = w2h; ol = w2l; j = i - GW3 - 2*GWS; }
        else                       { src = r3; oh = w3h; ol = w3l; j = i - GW3 - 3*GWS; }
        float4 v0 = src[2*j], v1 = src[2*j+1];
        uint4 hi, lo;
        split8(v0, v1, hi, lo);
        oh[j] = hi; ol[j] = lo;
    }
}

// ---------------- multi-GEMM descriptor ----------------
// modes: 0 fp32 out ; 1 relu fp32 ; 2 gate acts ; 3 r3+cell fused ; 4 relu + bf16 pair out
struct GemmDesc {
    const __nv_bfloat16 *A1h, *A1l, *W1h, *W1l;
    const __nv_bfloat16 *A2h, *A2l, *W2h, *W2l;
    const float *b1, *b2;
    float* Cf; __nv_bfloat16* Chi; __nv_bfloat16* Clo;
    int lda1, ldw1, lda2, ldw2;
    int s1, s2;          // number of K=32 chunks per operand pair
    int ldc, mode, nx;
};
struct DescPack {
    GemmDesc d[6];
    int starts[7];
};

// mega grid layout
#define ALPHA_B0 2048
#define ALPHA_B1 2080
#define MEGA_BLOCKS 2592

// ---------------- persistent dependency-graph mega GEMM kernel ----------------
__global__ void __launch_bounds__(256, 2)
mega(const __grid_constant__ DescPack P,
     const float* __restrict__ gates, const float* __restrict__ c_prev,
     float* __restrict__ alphav, const float* __restrict__ ssg,
     float* __restrict__ out_h, float* __restrict__ out_c,
     const float* __restrict__ ahbuf, const float* __restrict__ a2w,
     const float* __restrict__ a2b)
{
    extern __shared__ char smem[];
    const int tid = threadIdx.x;
    const int bid = blockIdx.x;

    // ---- alpha reduction blocks ----
    if (bid >= ALPHA_B0 && bid < ALPHA_B1) {
        const int mc = bid - ALPHA_B0;
        spin_wait(&g_cnt[32 + mc], 8);                // ah row-block complete
        const int l8 = tid & 7, r0 = tid >> 3;
#pragma unroll
        for (int p = 0; p < 4; ++p) {
            const int m = mc * 128 + p * 32 + r0;
            float s = 0.f;
            for (int k = l8; k < 1024; k += 8)
                s += ahbuf[(size_t)m * 1024 + k] * a2w[k];
            s += __shfl_down_sync(0xffffffffu, s, 4);
            s += __shfl_down_sync(0xffffffffu, s, 2);
            s += __shfl_down_sync(0xffffffffu, s, 1);
            if (l8 == 0) alphav[m] = 1.f / (1.f + __expf(-(s + a2b[0])));
        }
        signal_cnt(&g_cnt[128 + mc]);
        return;
    }

    const uint32_t sbase = smem_u32(smem);
    const int wid = tid >> 5, lane = tid & 31;
    const int wm = wid >> 2, wn = wid & 3;

    int t = bid, di = 0;
    while (di + 1 < 6 && t >= P.starts[di + 1]) ++di;
    const GemmDesc& d = P.d[di];
    const int rel = t - P.starts[di];
    const int m0 = (rel / d.nx) * 128, n0 = (rel % d.nx) * 128;
    const int rb = m0 >> 7;
    const int s1 = d.s1, S = d.s1 + d.s2;

    // mainloop input dependencies
    if (di == 4) spin_wait(&g_cnt[96 + rb], 8);       // r2 waits r1 row-block
    if (di == 5) spin_wait(&g_cnt[160 + rb], 8);      // r3 waits r2 row-block

    float acc[4][4][4];
#pragma unroll
    for (int a = 0; a < 4; ++a)
#pragma unroll
        for (int b = 0; b < 4; ++b)
#pragma unroll
            for (int q = 0; q < 4; ++q) acc[a][b][q] = 0.f;

    auto issue_load = [&](int s) {
        const __nv_bfloat16 *Ah, *Al, *Wh, *Wl; int lda, ldw, koff;
        if (s < s1) { Ah = d.A1h; Al = d.A1l; Wh = d.W1h; Wl = d.W1l; lda = d.lda1; ldw = d.ldw1; koff = s * 32; }
        else        { Ah = d.A2h; Al = d.A2l; Wh = d.W2h; Wl = d.W2l; lda = d.lda2; ldw = d.ldw2; koff = (s - s1) * 32; }
        const __nv_bfloat16* srcs[4] = {Ah, Al, Wh, Wl};
        uint32_t dst0 = sbase + (uint32_t)(s & 1) * STG_BYTES;
#pragma unroll
        for (int arr = 0; arr < 4; ++arr) {
            const __nv_bfloat16* src = srcs[arr];
            int ldx = (arr < 2) ? lda : ldw;
#pragma unroll
            for (int i = 0; i < 2; ++i) {
                int idx = tid + i * 256;
                int row = idx >> 2, c = idx & 3;
                int rbase = (arr < 2) ? m0 : n0;
                const __nv_bfloat16* g = src + (size_t)(rbase + row) * ldx + koff + c * 8;
                uint32_t dsta = dst0 + arr * ARR_BYTES + row * 80 + c * 16;
                CP_ASYNC16(dsta, g);
            }
        }
        CP_COMMIT();
    };

    issue_load(0);

    for (int s = 0; s < S; ++s) {
        CP_WAIT(0);              // only group s is in flight here; wait for it
        __syncthreads();         // all warps done compute(s-1) -> buf (s+1)&1 free; stage-s data visible

        uint32_t SB = sbase + (uint32_t)(s & 1) * STG_BYTES;
        uint32_t Ahb = SB, Alb = SB + ARR_BYTES;
        uint32_t Whb = SB + 2 * ARR_BYTES, Wlb = SB + 3 * ARR_BYTES;

#pragma unroll
        for (int k16 = 0; k16 < 2; ++k16) {
            const int k0 = k16 * 16;
            uint32_t bh[4][2], bl[4][2];
            {
                const int g = lane >> 3;
                const int rbw = wn * 32 + ((g >> 1) << 3) + (lane & 7);
                const int cb = k0 + ((g & 1) << 3);
#pragma unroll
                for (int p = 0; p < 2; ++p) {
                    uint32_t off = (uint32_t)((rbw + p * 16) * RS + cb) * 2;
                    ldsm4(bh[2*p][0], bh[2*p][1], bh[2*p+1][0], bh[2*p+1][1], Whb + off);
                    ldsm4(bl[2*p][0], bl[2*p][1], bl[2*p+1][0], bl[2*p+1][1], Wlb + off);
                }
            }
            const int ra = wm * 64 + (lane & 15);
            const int ca = k0 + ((lane >> 4) << 3);
            uint32_t ah[2][4], al[2][4];
            {
                uint32_t off0 = (uint32_t)(ra * RS + ca) * 2;
                ldsm4(ah[0][0], ah[0][1], ah[0][2], ah[0][3], Ahb + off0);
                ldsm4(al[0][0], al[0][1], al[0][2], al[0][3], Alb + off0);
            }
            // issue next stage's cp.asyncs in the shadow of the in-flight ldsm loads
            if (k16 == 0 && s + 1 < S) issue_load(s + 1);
#pragma unroll
            for (int mb = 0; mb < 4; ++mb) {
                const int cur = mb & 1, nxt = cur ^ 1;
                if (mb < 3) {
                    uint32_t off = (uint32_t)((ra + (mb + 1) * 16) * RS + ca) * 2;
                    ldsm4(ah[nxt][0], ah[nxt][1], ah[nxt][2], ah[nxt][3], Ahb + off);
                    ldsm4(al[nxt][0], al[nxt][1], al[nxt][2], al[nxt][3], Alb + off);
                }
#pragma unroll
                for (int nb = 0; nb < 4; ++nb) mma16816(acc[mb][nb], ah[cur], bh[nb]);
#pragma unroll
                for (int nb = 0; nb < 4; ++nb) mma16816(acc[mb][nb], ah[cur], bl[nb]);
#pragma unroll
                for (int nb = 0; nb < 4; ++nb) mma16816(acc[mb][nb], al[cur], bh[nb]);
            }
        }
        // no bottom barrier: next iteration's top barrier covers the WAR on buf s&1
    }

    // r3 epilogue dependencies (deferred past mainloop for overlap)
    if (di == 5) {
        spin_wait(&g_cnt[0 + rb], 40);    // gates row-block
        spin_wait(&g_cnt[64 + rb], 8);    // ssg row-block
        spin_wait(&g_cnt[128 + rb], 1);   // alpha chunk
    }

    // ---------------- epilogue ----------------
    const int mode = d.mode;
#pragma unroll
    for (int mb = 0; mb < 4; ++mb) {
#pragma unroll
        for (int nb = 0; nb < 4; ++nb) {
#pragma unroll
            for (int h = 0; h < 2; ++h) {
                const int m = m0 + wm * 64 + mb * 16 + (lane >> 2) + h * 8;
                const int n = n0 + wn * 32 + nb * 8 + 2 * (lane & 3);
                float v0 = acc[mb][nb][2 * h]     + d.b1[n];
                float v1 = acc[mb][nb][2 * h + 1] + d.b1[n + 1];
                if (d.b2) { v0 += d.b2[n]; v1 += d.b2[n + 1]; }
                if (mode == 1 || mode == 4) { v0 = fmaxf(v0, 0.f); v1 = fmaxf(v1, 0.f); }
                if (mode == 2) {
                    const int g = n >> 10;
                    if (g == 3) { v0 = tanh_fast(v0); v1 = tanh_fast(v1); }
                    else { v0 = 1.f / (1.f + __expf(-v0)); v1 = 1.f / (1.f + __expf(-v1)); }
                }
                const size_t gm = (size_t)m * d.ldc + n;
                if (mode == 4) {
                    __nv_bfloat162 hi2, lo2;
                    split2(v0, v1, hi2, lo2);
                    *(__nv_bfloat162*)(d.Chi + gm) = hi2;
                    *(__nv_bfloat162*)(d.Clo + gm) = lo2;
                } else if (mode == 3) {
                    const size_t gb = (size_t)m * NG + n;
                    const float a = alphav[m];
                    float2 cp = *(const float2*)(c_prev + gm);
                    float2 sg = *(const float2*)(ssg + gm);
                    float c0 = gates[gb + 1024] * cp.x
                             + gates[gb] * gates[gb + 3072] * gates[gb + 4096] * a * sg.x + v0;
                    float c1 = gates[gb + 1025] * cp.y
                             + gates[gb + 1] * gates[gb + 3073] * gates[gb + 4097] * a * sg.y + v1;
                    float2 oc; oc.x = c0; oc.y = c1;
                    float2 oh; oh.x = gates[gb + 2048] * tanh_fast(c0);
                    oh.y = gates[gb + 2049] * tanh_fast(c1);
                    *(float2*)(out_c + gm) = oc;
                    *(float2*)(out_h + gm) = oh;
                } else {
                    float2 o; o.x = v0; o.y = v1;
                    *(float2*)(d.Cf + gm) = o;
                }
            }
        }
    }

    // completion signals
    if      (di == 0) signal_cnt(&g_cnt[0 + rb]);
    else if (di == 1) signal_cnt(&g_cnt[32 + rb]);
    else if (di == 2) signal_cnt(&g_cnt[64 + rb]);
    else if (di == 3) signal_cnt(&g_cnt[96 + rb]);
    else if (di == 4) signal_cnt(&g_cnt[160 + rb]);
}

// ---------------- launch ----------------
extern "C" void kernel_launch(void* const* d_in, const int* in_sizes, int n_in,
                              void* d_out, int out_size)
{
    const float* x      = (const float*)d_in[0];
    const float* h_prev = (const float*)d_in[1];
    const float* c_prev = (const float*)d_in[2];
    const float* ssg_st = (const float*)d_in[3];
    const float* Wx     = (const float*)d_in[4];
    const float* bWx    = (const float*)d_in[5];
    const float* Ux     = (const float*)d_in[6];
    const float* bUx    = (const float*)d_in[7];
    const float* a1_w   = (const float*)d_in[8];
    const float* a1_b   = (const float*)d_in[9];
    const float* a2_w   = (const float*)d_in[10];
    const float* a2_b   = (const float*)d_in[11];
    const float* r1_w   = (const float*)d_in[12];
    const float* r1_b   = (const float*)d_in[13];
    const float* r2_w   = (const float*)d_in[14];
    const float* r2_b   = (const float*)d_in[15];
    const float* r3_w   = (const float*)d_in[16];
    const float* r3_b   = (const float*)d_in[17];
    const float* ssg_w  = (const float*)d_in[18];
    const float* ssg_b  = (const float*)d_in[19];

    float* out = (float*)d_out;
    float* out_h   = out;
    float* out_c   = out + (size_t)BH;
    float* out_ssg = out + 2 * (size_t)BH;

    __nv_bfloat16 *xh, *xl, *hh, *hl, *sgh, *sgl, *r1h, *r1l, *r2h, *r2l;
    __nv_bfloat16 *Wxh, *Wxl, *Uxh, *Uxl, *a1h, *a1l, *swh, *swl, *w1h, *w1l, *w2h, *w2l, *w3h, *w3l;
    float *gates, *ah, *alpha;
    cudaGetSymbolAddress((void**)&xh, s_x_hi);   cudaGetSymbolAddress((void**)&xl, s_x_lo);
    cudaGetSymbolAddress((void**)&hh, s_h_hi);   cudaGetSymbolAddress((void**)&hl, s_h_lo);
    cudaGetSymbolAddress((void**)&sgh, s_sg_hi); cudaGetSymbolAddress((void**)&sgl, s_sg_lo);
    cudaGetSymbolAddress((void**)&r1h, s_r1_hi); cudaGetSymbolAddress((void**)&r1l, s_r1_lo);
    cudaGetSymbolAddress((void**)&r2h, s_r2_hi); cudaGetSymbolAddress((void**)&r2l, s_r2_lo);
    cudaGetSymbolAddress((void**)&Wxh, w_Wx_hi); cudaGetSymbolAddress((void**)&Wxl, w_Wx_lo);
    cudaGetSymbolAddress((void**)&Uxh, w_Ux_hi); cudaGetSymbolAddress((void**)&Uxl, w_Ux_lo);
    cudaGetSymbolAddress((void**)&a1h, w_a1_hi); cudaGetSymbolAddress((void**)&a1l, w_a1_lo);
    cudaGetSymbolAddress((void**)&swh, w_sw_hi); cudaGetSymbolAddress((void**)&swl, w_sw_lo);
    cudaGetSymbolAddress((void**)&w1h, w_r1_hi); cudaGetSymbolAddress((void**)&w1l, w_r1_lo);
    cudaGetSymbolAddress((void**)&w2h, w_r2_hi); cudaGetSymbolAddress((void**)&w2l, w_r2_lo);
    cudaGetSymbolAddress((void**)&w3h, w_r3_hi); cudaGetSymbolAddress((void**)&w3l, w_r3_lo);
    cudaGetSymbolAddress((void**)&gates, g_gates);
    cudaGetSymbolAddress((void**)&ah, g_ah);
    cudaGetSymbolAddress((void**)&alpha, g_alpha);

    cudaFuncSetAttribute(mega, cudaFuncAttributeMaxDynamicSharedMemorySize, SMEM_BYTES);

    const dim3 blk(256);

    // launch 1: all conversions + counter zeroing
    cvt_all<<<CVT_TOT, blk>>>((const float4*)x, (const float4*)h_prev, (const float4*)ssg_st,
                              (const float4*)Wx, (const float4*)Ux, (const float4*)a1_w,
                              (const float4*)ssg_w, (const float4*)r1_w,
                              (const float4*)r2_w, (const float4*)r3_w,
                              (uint4*)xh, (uint4*)xl, (uint4*)hh, (uint4*)hl,
                              (uint4*)sgh, (uint4*)sgl,
                              (uint4*)Wxh, (uint4*)Wxl, (uint4*)Uxh, (uint4*)Uxl,
                              (uint4*)a1h, (uint4*)a1l, (uint4*)swh, (uint4*)swl,
                              (uint4*)w1h, (uint4*)w1l, (uint4*)w2h, (uint4*)w2l,
                              (uint4*)w3h, (uint4*)w3l);

    // launch 2: mega dependency-graph GEMM schedule
    DescPack P = {};
    P.d[0] = { xh, xl, Wxh, Wxl, hh, hl, Uxh, Uxl, bWx, bUx,
               gates, nullptr, nullptr, 1024, 1024, 1024, 1024, 32, 32, NG, 2, NG/128 };
    P.d[1] = { xh, xl, a1h, a1l, hh, hl, a1h + 1024, a1l + 1024, a1_b, nullptr,
               ah, nullptr, nullptr, 1024, 2048, 1024, 2048, 32, 32, HH, 1, HH/128 };
    P.d[2] = { sgh, sgl, swh, swl, nullptr, nullptr, nullptr, nullptr, ssg_b, nullptr,
               out_ssg, nullptr, nullptr, 1024, 1024, 0, 0, 32, 0, HH, 0, HH/128 };
    P.d[3] = { hh, hl, w1h, w1l, nullptr, nullptr, nullptr, nullptr, r1_b, nullptr,
               nullptr, r1h, r1l, 1024, 1024, 0, 0, 32, 0, HH, 4, HH/128 };
    P.d[4] = { r1h, r1l, w2h, w2l, nullptr, nullptr, nullptr, nullptr, r2_b, nullptr,
               nullptr, r2h, r2l, 1024, 1024, 0, 0, 32, 0, HH, 4, HH/128 };
    P.d[5] = { r2h, r2l, w3h, w3l, nullptr, nullptr, nullptr, nullptr, r3_b, nullptr,
               nullptr, nullptr, nullptr, 1024, 1024, 0, 0, 32, 0, HH, 3, HH/128 };
    P.starts[0] = 0;    P.starts[1] = 1280; P.starts[2] = 1536; P.starts[3] = 1792;
    P.starts[4] = 2080; P.starts[5] = 2336; P.starts[6] = 2592;

    mega<<<MEGA_BLOCKS, blk, SMEM_BYTES>>>(P, gates, c_prev, alpha, out_ssg,
                                           out_h, out_c, ah, a2_w, a2_b);
}